// round 1
// baseline (speedup 1.0000x reference)
#include <cuda_runtime.h>
#include <math.h>

#define N_NODES 50000
#define N_EDGES 1600000
#define FDIM 128
#define KDIM 512
#define JDIM 512

// ---------------- device scratch (no allocations allowed) ----------------
__device__ float  g_deg[N_NODES];
__device__ float  g_negnorm[N_NODES];
__device__ float4 g_xs[N_NODES * 32];    // x * norm  (row-scaled)
__device__ float4 g_hs[N_NODES * 32];    // hx * norm
__device__ float4 g_aggx[N_NODES * 32];  // segment sums
__device__ float4 g_aggh[N_NODES * 32];
__device__ float  g_Wcat[KDIM * JDIM];   // concatenated weights [512 x 512]
__device__ float  g_G[(size_t)N_NODES * JDIM];  // GEMM output [N x 512]

// ---------------- kernels ----------------

// zero deg + agg buffers (agg as float4: 2 * 1.6M float4; deg: 50000 floats)
__global__ void k_zero() {
    int i = blockIdx.x * blockDim.x + threadIdx.x;
    const int NAGG = N_NODES * 32;  // 1.6M float4 each
    if (i < NAGG) {
        g_aggx[i] = make_float4(0.f, 0.f, 0.f, 0.f);
        g_aggh[i] = make_float4(0.f, 0.f, 0.f, 0.f);
    }
    if (i < N_NODES) g_deg[i] = 0.f;
}

__global__ void k_deg(const int* __restrict__ ei) {
    int e = blockIdx.x * blockDim.x + threadIdx.x;
    if (e < N_EDGES) {
        int dst = __ldg(&ei[N_EDGES + e]);
        atomicAdd(&g_deg[dst], 1.0f);
    }
}

// norm = rsqrt(max(deg,1)); xs = x*norm; hs = hx*norm; store -norm
__global__ void k_scale(const float4* __restrict__ x4, const float4* __restrict__ h4) {
    int i = blockIdx.x * blockDim.x + threadIdx.x;  // over N*32 float4
    if (i >= N_NODES * 32) return;
    int n = i >> 5;
    float nrm = rsqrtf(fmaxf(g_deg[n], 1.0f));
    if ((i & 31) == 0) g_negnorm[n] = -nrm;
    float4 xv = x4[i];
    xv.x *= nrm; xv.y *= nrm; xv.z *= nrm; xv.w *= nrm;
    g_xs[i] = xv;
    float4 hv = h4[i];
    hv.x *= nrm; hv.y *= nrm; hv.z *= nrm; hv.w *= nrm;
    g_hs[i] = hv;
}

__device__ __forceinline__ void red4(float4* p, float4 v) {
    asm volatile("red.global.add.v4.f32 [%0], {%1, %2, %3, %4};"
                 :: "l"(p), "f"(v.x), "f"(v.y), "f"(v.z), "f"(v.w) : "memory");
}

// one warp per edge: lane l handles float4 chunk l of both xs and hs rows
__global__ __launch_bounds__(256) void k_scatter(const int* __restrict__ ei) {
    int gt = blockIdx.x * blockDim.x + threadIdx.x;
    int e = gt >> 5;
    int lane = threadIdx.x & 31;
    if (e >= N_EDGES) return;
    int src = __ldg(&ei[e]);
    int dst = __ldg(&ei[N_EDGES + e]);
    float4 v = g_xs[src * 32 + lane];
    red4(&g_aggx[dst * 32 + lane], v);
    float4 h = g_hs[src * 32 + lane];
    red4(&g_aggh[dst * 32 + lane], h);
}

// build concatenated weight matrix [k=512][j=512]
// k blocks: 0:x 1:px 2:hx 3:ph ; j blocks: 0:R 1:U 2:Cx 3:Ch
__global__ void k_wcat(const float* __restrict__ W_rx, const float* __restrict__ W_rh,
                       const float* __restrict__ W_ux, const float* __restrict__ W_uh,
                       const float* __restrict__ W_cx, const float* __restrict__ W_ch) {
    int idx = blockIdx.x * blockDim.x + threadIdx.x;
    if (idx >= KDIM * JDIM) return;
    int k = idx >> 9, j = idx & 511;
    int kb = k >> 7, jb = j >> 7;
    int f = k & 127, h = j & 127;
    const float* src = nullptr;
    if (jb == 0)      src = (kb < 2) ? W_rx : W_rh;
    else if (jb == 1) src = (kb < 2) ? W_ux : W_uh;
    else if (jb == 2) src = (kb < 2) ? W_cx : nullptr;
    else              src = (kb >= 2) ? W_ch : nullptr;
    int t = kb & 1;
    float v = src ? src[t * (FDIM * FDIM) + f * FDIM + h] : 0.f;
    g_Wcat[k * JDIM + j] = v;
}

// SGEMM: G[N,512] = A[N,512] @ Wcat[512,512]
// A is virtual: k-block 0 = x, 1 = aggx * (-norm[row]), 2 = hx, 3 = aggh * (-norm[row])
__global__ __launch_bounds__(256) void k_gemm(const float4* __restrict__ x4,
                                              const float4* __restrict__ h4) {
    __shared__ float As[16][132];
    __shared__ float Bs[16][128];

    int row0 = blockIdx.x * 128;
    int bn = blockIdx.y;              // col tile (0..3)
    int tid = threadIdx.x;

    float acc[8][8];
#pragma unroll
    for (int i = 0; i < 8; i++)
#pragma unroll
        for (int j = 0; j < 8; j++) acc[i][j] = 0.f;

    int trow = (tid >> 4) << 3;
    int tcol = (tid & 15) << 3;

    const float4* g_aggx4 = g_aggx;
    const float4* g_aggh4 = g_aggh;
    const float4* wc4 = (const float4*)g_Wcat;

    for (int k0 = 0; k0 < KDIM; k0 += 16) {
        int blk = k0 >> 7;           // which 128-block of K
        int koff4 = (k0 & 127) >> 2; // float4 offset within the 128-block
        const float4* srcA = (blk == 0) ? x4 : (blk == 1) ? g_aggx4 : (blk == 2) ? h4 : g_aggh4;
        bool scaled = (blk & 1);

        // load A tile: 128 rows x 16 cols = 512 float4, 2 per thread
#pragma unroll
        for (int rep = 0; rep < 2; rep++) {
            int la = tid + rep * 256;
            int ar = la >> 2;
            int ac4 = la & 3;
            int row = row0 + ar;
            float4 v = make_float4(0.f, 0.f, 0.f, 0.f);
            if (row < N_NODES) {
                v = srcA[row * 32 + koff4 + ac4];
                if (scaled) {
                    float s = g_negnorm[row];
                    v.x *= s; v.y *= s; v.z *= s; v.w *= s;
                }
            }
            int kk = ac4 << 2;
            As[kk + 0][ar] = v.x;
            As[kk + 1][ar] = v.y;
            As[kk + 2][ar] = v.z;
            As[kk + 3][ar] = v.w;
        }
        // load B tile: 16 rows x 128 cols = 512 float4
#pragma unroll
        for (int rep = 0; rep < 2; rep++) {
            int lb = tid + rep * 256;
            int br = lb >> 5;
            int bc4 = lb & 31;
            float4 w = wc4[((k0 + br) * JDIM + bn * 128) / 4 + bc4];
            *(float4*)&Bs[br][bc4 << 2] = w;
        }
        __syncthreads();

#pragma unroll
        for (int kk = 0; kk < 16; kk++) {
            float a[8], b[8];
#pragma unroll
            for (int i = 0; i < 8; i++) a[i] = As[kk][trow + i];
#pragma unroll
            for (int j = 0; j < 8; j++) b[j] = Bs[kk][tcol + j];
#pragma unroll
            for (int i = 0; i < 8; i++)
#pragma unroll
                for (int j = 0; j < 8; j++) acc[i][j] = fmaf(a[i], b[j], acc[i][j]);
        }
        __syncthreads();
    }

#pragma unroll
    for (int i = 0; i < 8; i++) {
        int row = row0 + trow + i;
        if (row < N_NODES) {
            float* gp = &g_G[(size_t)row * JDIM + bn * 128 + tcol];
            *(float4*)gp       = make_float4(acc[i][0], acc[i][1], acc[i][2], acc[i][3]);
            *(float4*)(gp + 4) = make_float4(acc[i][4], acc[i][5], acc[i][6], acc[i][7]);
        }
    }
}

__device__ __forceinline__ float sigm(float z) { return 1.0f / (1.0f + expf(-z)); }

__global__ void k_epilogue(const float* __restrict__ hx,
                           const float* __restrict__ b_rx, const float* __restrict__ b_rh,
                           const float* __restrict__ b_ux, const float* __restrict__ b_uh,
                           const float* __restrict__ b_cx, const float* __restrict__ b_ch,
                           float* __restrict__ out) {
    int idx = blockIdx.x * blockDim.x + threadIdx.x;
    if (idx >= N_NODES * FDIM) return;
    int n = idx >> 7, h = idx & 127;
    const float* g = &g_G[(size_t)n * JDIM];
    float R  = g[h];
    float U  = g[128 + h];
    float Cx = g[256 + h];
    float Ch = g[384 + h];
    float r = sigm(R + b_rx[h] + b_rh[h]);
    float u = sigm(U + b_ux[h] + b_uh[h]);
    float c = sigm(Cx + b_cx[h] + (Ch + b_ch[h]) * r);
    out[idx] = u * hx[idx] + (1.0f - u) * c;
}

// ---------------- launch ----------------
extern "C" void kernel_launch(void* const* d_in, const int* in_sizes, int n_in,
                              void* d_out, int out_size) {
    const int*   ei   = (const int*)d_in[0];
    const float* x    = (const float*)d_in[1];
    const float* hx   = (const float*)d_in[2];
    const float* W_rx = (const float*)d_in[3];
    const float* b_rx = (const float*)d_in[4];
    const float* W_rh = (const float*)d_in[5];
    const float* b_rh = (const float*)d_in[6];
    const float* W_ux = (const float*)d_in[7];
    const float* b_ux = (const float*)d_in[8];
    const float* W_uh = (const float*)d_in[9];
    const float* b_uh = (const float*)d_in[10];
    const float* W_cx = (const float*)d_in[11];
    const float* b_cx = (const float*)d_in[12];
    const float* W_ch = (const float*)d_in[13];
    const float* b_ch = (const float*)d_in[14];
    float* out = (float*)d_out;

    // 1) zero scratch
    {
        int n = N_NODES * 32;  // float4 count per agg buffer
        k_zero<<<(n + 255) / 256, 256>>>();
    }
    // 2) degree
    k_deg<<<(N_EDGES + 255) / 256, 256>>>(ei);
    // 3) norm + scaled copies
    k_scale<<<(N_NODES * 32 + 255) / 256, 256>>>((const float4*)x, (const float4*)hx);
    // 4) edge scatter (warp per edge)
    {
        long long threads = (long long)N_EDGES * 32;
        k_scatter<<<(int)((threads + 255) / 256), 256>>>(ei);
    }
    // 5) concatenated weights
    k_wcat<<<(KDIM * JDIM + 255) / 256, 256>>>(W_rx, W_rh, W_ux, W_uh, W_cx, W_ch);
    // 6) big GEMM
    {
        dim3 grid((N_NODES + 127) / 128, 4);
        k_gemm<<<grid, 256>>>((const float4*)x, (const float4*)hx);
    }
    // 7) fused gates + GRU update
    k_epilogue<<<(N_NODES * FDIM + 255) / 256, 256>>>(hx, b_rx, b_rh, b_ux, b_uh,
                                                      b_cx, b_ch, out);
}

// round 3
// speedup vs baseline: 1.4648x; 1.4648x over previous
#include <cuda_runtime.h>
#include <cuda_bf16.h>
#include <math.h>
#include <stdint.h>

#define N_NODES 50000
#define N_EDGES 1600000
#define FDIM 128
#define KDIM 512
#define JDIM 512

// ---------------- device scratch (no allocations allowed) ----------------
__device__ float  g_deg[N_NODES];
__device__ float  g_negnorm[N_NODES];
__device__ float4 g_xs[N_NODES * 32];    // x * norm  (row-scaled, for scatter)
__device__ float4 g_hs[N_NODES * 32];    // hx * norm
__device__ float4 g_aggx[N_NODES * 32];  // segment sums
__device__ float4 g_aggh[N_NODES * 32];
__device__ __nv_bfloat16 g_Wb_hi[KDIM * JDIM];  // W^T [n=512][k=512], hi part
__device__ __nv_bfloat16 g_Wb_lo[KDIM * JDIM];  // lo part
__device__ float  g_G[(size_t)N_NODES * JDIM];  // GEMM output [N x 512]

// ---------------- helpers ----------------
__device__ __forceinline__ uint32_t smem_u32(const void* p) {
    uint32_t a;
    asm("{ .reg .u64 t; cvta.to.shared.u64 t, %1; cvt.u32.u64 %0, t; }" : "=r"(a) : "l"(p));
    return a;
}
#define SWZ128(off) ((off) ^ (((off) >> 3) & 0x70))

__device__ __forceinline__ void ldsm_x4(uint32_t addr, uint32_t& r0, uint32_t& r1,
                                        uint32_t& r2, uint32_t& r3) {
    asm volatile("ldmatrix.sync.aligned.m8n8.x4.shared.b16 {%0,%1,%2,%3}, [%4];"
                 : "=r"(r0), "=r"(r1), "=r"(r2), "=r"(r3) : "r"(addr));
}

__device__ __forceinline__ void mma_bf16(float& d0, float& d1, float& d2, float& d3,
                                         uint32_t a0, uint32_t a1, uint32_t a2, uint32_t a3,
                                         uint32_t b0, uint32_t b1) {
    asm volatile(
        "mma.sync.aligned.m16n8k16.row.col.f32.bf16.bf16.f32 "
        "{%0,%1,%2,%3}, {%4,%5,%6,%7}, {%8,%9}, {%0,%1,%2,%3};"
        : "+f"(d0), "+f"(d1), "+f"(d2), "+f"(d3)
        : "r"(a0), "r"(a1), "r"(a2), "r"(a3), "r"(b0), "r"(b1));
}

__device__ __forceinline__ void split2(float a, float b, uint32_t& hi, uint32_t& lo) {
    __nv_bfloat16 ah = __float2bfloat16(a), bh = __float2bfloat16(b);
    __nv_bfloat16 al = __float2bfloat16(a - __bfloat162float(ah));
    __nv_bfloat16 bl = __float2bfloat16(b - __bfloat162float(bh));
    hi = ((uint32_t)__bfloat16_as_ushort(bh) << 16) | (uint32_t)__bfloat16_as_ushort(ah);
    lo = ((uint32_t)__bfloat16_as_ushort(bl) << 16) | (uint32_t)__bfloat16_as_ushort(al);
}

// ---------------- graph kernels ----------------
__global__ void k_zero() {
    int i = blockIdx.x * blockDim.x + threadIdx.x;
    const int NAGG = N_NODES * 32;
    if (i < NAGG) {
        g_aggx[i] = make_float4(0.f, 0.f, 0.f, 0.f);
        g_aggh[i] = make_float4(0.f, 0.f, 0.f, 0.f);
    }
    if (i < N_NODES) g_deg[i] = 0.f;
}

__global__ void k_deg(const int* __restrict__ ei) {
    int e = blockIdx.x * blockDim.x + threadIdx.x;
    if (e < N_EDGES) {
        int dst = __ldg(&ei[N_EDGES + e]);
        atomicAdd(&g_deg[dst], 1.0f);
    }
}

__global__ void k_scale(const float4* __restrict__ x4, const float4* __restrict__ h4) {
    int i = blockIdx.x * blockDim.x + threadIdx.x;
    if (i >= N_NODES * 32) return;
    int n = i >> 5;
    float nrm = rsqrtf(fmaxf(g_deg[n], 1.0f));
    if ((i & 31) == 0) g_negnorm[n] = -nrm;
    float4 xv = x4[i];
    xv.x *= nrm; xv.y *= nrm; xv.z *= nrm; xv.w *= nrm;
    g_xs[i] = xv;
    float4 hv = h4[i];
    hv.x *= nrm; hv.y *= nrm; hv.z *= nrm; hv.w *= nrm;
    g_hs[i] = hv;
}

__device__ __forceinline__ void red4(float4* p, float4 v) {
    asm volatile("red.global.add.v4.f32 [%0], {%1, %2, %3, %4};"
                 :: "l"(p), "f"(v.x), "f"(v.y), "f"(v.z), "f"(v.w) : "memory");
}

__global__ __launch_bounds__(256) void k_scatter(const int* __restrict__ ei) {
    int gt = blockIdx.x * blockDim.x + threadIdx.x;
    int e = gt >> 5;
    int lane = threadIdx.x & 31;
    if (e >= N_EDGES) return;
    int src = __ldg(&ei[e]);
    int dst = __ldg(&ei[N_EDGES + e]);
    float4 v = g_xs[src * 32 + lane];
    red4(&g_aggx[dst * 32 + lane], v);
    float4 h = g_hs[src * 32 + lane];
    red4(&g_aggh[dst * 32 + lane], h);
}

// W^T concat, split into bf16 hi/lo. Layout: [n=512][k=512], K contiguous.
// k blocks: 0:x 1:px 2:hx 3:ph ; n blocks: 0:R 1:U 2:Cx 3:Ch
__global__ void k_wcat(const float* __restrict__ W_rx, const float* __restrict__ W_rh,
                       const float* __restrict__ W_ux, const float* __restrict__ W_uh,
                       const float* __restrict__ W_cx, const float* __restrict__ W_ch) {
    int idx = blockIdx.x * blockDim.x + threadIdx.x;
    if (idx >= KDIM * JDIM) return;
    int n = idx >> 9, k = idx & 511;
    int kb = k >> 7, jb = n >> 7;
    int f = k & 127, h = n & 127;
    const float* src = nullptr;
    if (jb == 0)      src = (kb < 2) ? W_rx : W_rh;
    else if (jb == 1) src = (kb < 2) ? W_ux : W_uh;
    else if (jb == 2) src = (kb < 2) ? W_cx : nullptr;
    else              src = (kb >= 2) ? W_ch : nullptr;
    float v = src ? src[(kb & 1) * (FDIM * FDIM) + f * FDIM + h] : 0.f;
    __nv_bfloat16 hi = __float2bfloat16(v);
    __nv_bfloat16 lo = __float2bfloat16(v - __bfloat162float(hi));
    g_Wb_hi[idx] = hi;
    g_Wb_lo[idx] = lo;
}

// ---------------- HMMA GEMM ----------------
// G[128 rows x 128 cols per CTA] = A[128,512] (virtual, hi/lo bf16 split)
//                                  @ W[512, n-strip 128] (hi/lo bf16)
// grid(391, 4), 256 threads (8 warps, warp tile 64x32).
// smem tiles per K-step of 64: A_HI/A_LO [128][64] bf16 SW128, B_HI/B_LO [128n][64k] bf16 SW128.

#define SA_HI 0
#define SA_LO 16384
#define SB_HI 32768
#define SB_LO 49152
#define SMEM_GEMM 65536

__global__ __launch_bounds__(256, 1) void k_gemm_mma(const float4* __restrict__ x4,
                                                     const float4* __restrict__ h4) {
    extern __shared__ char smem[];
    uint32_t sb = smem_u32(smem);
    int tid = threadIdx.x, wid = tid >> 5, lane = tid & 31;
    int row0 = blockIdx.x * 128;
    int n0g = blockIdx.y * 128;
    int wm = (wid & 1) * 64;   // warp m offset
    int wn = (wid >> 1) * 32;  // warp n offset

    float d[4][4][4];
#pragma unroll
    for (int i = 0; i < 4; i++)
#pragma unroll
        for (int j = 0; j < 4; j++)
#pragma unroll
            for (int q = 0; q < 4; q++) d[i][j][q] = 0.f;

    // precomputed per-lane ldmatrix address components
    int a_row = wm + (lane & 15);            // + mf*16
    int a_kb  = (lane >> 4) * 16;            // + kk*32
    int b_row = wn + (lane & 7) + ((lane >> 4) << 3);  // + pf*16
    int b_kb  = ((lane >> 3) & 1) * 16;      // + kk*32

    const char* wb_hi = (const char*)g_Wb_hi;
    const char* wb_lo = (const char*)g_Wb_lo;

#pragma unroll 1
    for (int s = 0; s < 8; s++) {
        int k0 = s * 64;
        int blk = s >> 1, half = s & 1;
        const float4* srcA = (blk == 0) ? x4 : (blk == 1) ? (const float4*)g_aggx
                           : (blk == 2) ? h4 : (const float4*)g_aggh;
        bool scaled = (blk & 1);

        // ---- A tile: 128 rows x 64 fp32 -> bf16 hi/lo ----
#pragma unroll
        for (int it = 0; it < 8; it++) {
            int id = tid + it * 256;
            int r = id >> 4, c4 = id & 15;
            int row = row0 + r;
            float4 v = make_float4(0.f, 0.f, 0.f, 0.f);
            if (row < N_NODES) {
                v = srcA[row * 32 + half * 16 + c4];
                if (scaled) {
                    float sc = g_negnorm[row];
                    v.x *= sc; v.y *= sc; v.z *= sc; v.w *= sc;
                }
            }
            uint32_t h01, l01, h23, l23;
            split2(v.x, v.y, h01, l01);
            split2(v.z, v.w, h23, l23);
            uint32_t off = SWZ128((uint32_t)(r * 128 + c4 * 8));
            *(uint2*)(smem + SA_HI + off) = make_uint2(h01, h23);
            *(uint2*)(smem + SA_LO + off) = make_uint2(l01, l23);
        }
        // ---- B tile: 128 n-rows x 64 k bf16 (hi & lo) ----
#pragma unroll
        for (int it = 0; it < 4; it++) {
            int id = tid + it * 256;
            int n = id >> 3, c = id & 7;
            long gb = ((long)(n0g + n) * 512 + k0) * 2 + c * 16;
            uint32_t off = SWZ128((uint32_t)(n * 128 + c * 16));
            *(uint4*)(smem + SB_HI + off) = *(const uint4*)(wb_hi + gb);
            *(uint4*)(smem + SB_LO + off) = *(const uint4*)(wb_lo + gb);
        }
        __syncthreads();

        // ---- compute: 4 k16 chunks ----
#pragma unroll
        for (int kk = 0; kk < 4; kk++) {
            uint32_t ah[4][4], al[4][4];
#pragma unroll
            for (int mf = 0; mf < 4; mf++) {
                uint32_t boff = SWZ128((uint32_t)((a_row + mf * 16) * 128 + kk * 32 + a_kb));
                ldsm_x4(sb + SA_HI + boff, ah[mf][0], ah[mf][1], ah[mf][2], ah[mf][3]);
                ldsm_x4(sb + SA_LO + boff, al[mf][0], al[mf][1], al[mf][2], al[mf][3]);
            }
            uint32_t bh[4][2], bl[4][2];
#pragma unroll
            for (int pf = 0; pf < 2; pf++) {
                uint32_t boff = SWZ128((uint32_t)((b_row + pf * 16) * 128 + kk * 32 + b_kb));
                ldsm_x4(sb + SB_HI + boff, bh[2 * pf][0], bh[2 * pf][1], bh[2 * pf + 1][0], bh[2 * pf + 1][1]);
                ldsm_x4(sb + SB_LO + boff, bl[2 * pf][0], bl[2 * pf][1], bl[2 * pf + 1][0], bl[2 * pf + 1][1]);
            }
#pragma unroll
            for (int mf = 0; mf < 4; mf++)
#pragma unroll
                for (int nf = 0; nf < 4; nf++) {
                    float* dd = d[mf][nf];
                    mma_bf16(dd[0], dd[1], dd[2], dd[3],
                             ah[mf][0], ah[mf][1], ah[mf][2], ah[mf][3],
                             bh[nf][0], bh[nf][1]);
                    mma_bf16(dd[0], dd[1], dd[2], dd[3],
                             al[mf][0], al[mf][1], al[mf][2], al[mf][3],
                             bh[nf][0], bh[nf][1]);
                    mma_bf16(dd[0], dd[1], dd[2], dd[3],
                             ah[mf][0], ah[mf][1], ah[mf][2], ah[mf][3],
                             bl[nf][0], bl[nf][1]);
                }
        }
        __syncthreads();
    }

    // ---- store G ----
#pragma unroll
    for (int mf = 0; mf < 4; mf++) {
        int r0 = row0 + wm + mf * 16 + (lane >> 2);
        int c0 = n0g + wn + (lane & 3) * 2;
#pragma unroll
        for (int nf = 0; nf < 4; nf++) {
            float* dd = d[mf][nf];
            int c = c0 + nf * 8;
            if (r0 < N_NODES)
                *(float2*)&g_G[(size_t)r0 * JDIM + c] = make_float2(dd[0], dd[1]);
            if (r0 + 8 < N_NODES)
                *(float2*)&g_G[(size_t)(r0 + 8) * JDIM + c] = make_float2(dd[2], dd[3]);
        }
    }
}

__device__ __forceinline__ float sigm(float z) { return 1.0f / (1.0f + expf(-z)); }

__global__ void k_epilogue(const float* __restrict__ hx,
                           const float* __restrict__ b_rx, const float* __restrict__ b_rh,
                           const float* __restrict__ b_ux, const float* __restrict__ b_uh,
                           const float* __restrict__ b_cx, const float* __restrict__ b_ch,
                           float* __restrict__ out) {
    int idx = blockIdx.x * blockDim.x + threadIdx.x;
    if (idx >= N_NODES * FDIM) return;
    int n = idx >> 7, h = idx & 127;
    const float* g = &g_G[(size_t)n * JDIM];
    float R  = g[h];
    float U  = g[128 + h];
    float Cx = g[256 + h];
    float Ch = g[384 + h];
    float r = sigm(R + b_rx[h] + b_rh[h]);
    float u = sigm(U + b_ux[h] + b_uh[h]);
    float c = sigm(Cx + b_cx[h] + (Ch + b_ch[h]) * r);
    out[idx] = u * hx[idx] + (1.0f - u) * c;
}

// ---------------- launch ----------------
extern "C" void kernel_launch(void* const* d_in, const int* in_sizes, int n_in,
                              void* d_out, int out_size) {
    const int*   ei   = (const int*)d_in[0];
    const float* x    = (const float*)d_in[1];
    const float* hx   = (const float*)d_in[2];
    const float* W_rx = (const float*)d_in[3];
    const float* b_rx = (const float*)d_in[4];
    const float* W_rh = (const float*)d_in[5];
    const float* b_rh = (const float*)d_in[6];
    const float* W_ux = (const float*)d_in[7];
    const float* b_ux = (const float*)d_in[8];
    const float* W_uh = (const float*)d_in[9];
    const float* b_uh = (const float*)d_in[10];
    const float* W_cx = (const float*)d_in[11];
    const float* b_cx = (const float*)d_in[12];
    const float* W_ch = (const float*)d_in[13];
    const float* b_ch = (const float*)d_in[14];
    float* out = (float*)d_out;

    cudaFuncSetAttribute(k_gemm_mma, cudaFuncAttributeMaxDynamicSharedMemorySize, SMEM_GEMM);

    // 1) zero scratch
    {
        int n = N_NODES * 32;
        k_zero<<<(n + 255) / 256, 256>>>();
    }
    // 2) degree
    k_deg<<<(N_EDGES + 255) / 256, 256>>>(ei);
    // 3) norm + scaled copies
    k_scale<<<(N_NODES * 32 + 255) / 256, 256>>>((const float4*)x, (const float4*)hx);
    // 4) edge scatter (warp per edge)
    {
        long long threads = (long long)N_EDGES * 32;
        k_scatter<<<(int)((threads + 255) / 256), 256>>>(ei);
    }
    // 5) concatenated transposed weights, bf16 hi/lo
    k_wcat<<<(KDIM * JDIM + 255) / 256, 256>>>(W_rx, W_rh, W_ux, W_uh, W_cx, W_ch);
    // 6) HMMA GEMM
    {
        dim3 grid((N_NODES + 127) / 128, 4);
        k_gemm_mma<<<grid, 256, SMEM_GEMM>>>((const float4*)x, (const float4*)hx);
    }
    // 7) fused gates + GRU update
    k_epilogue<<<(N_NODES * FDIM + 255) / 256, 256>>>(hx, b_rx, b_rh, b_ux, b_uh,
                                                      b_cx, b_ch, out);
}

// round 4
// speedup vs baseline: 2.5860x; 1.7655x over previous
#include <cuda_runtime.h>
#include <cuda_bf16.h>
#include <math.h>
#include <stdint.h>

#define N_NODES 50000
#define N_EDGES 1600000
#define FDIM 128
#define KDIM 512
#define JDIM 512

// ---------------- device scratch (no allocations allowed) ----------------
__device__ int    g_cnt[N_NODES];        // in-degree (int)
__device__ int    g_ptr[N_NODES];        // CSR row starts (exclusive scan)
__device__ int    g_cur[N_NODES];        // fill cursors
__device__ int    g_bsum[256];
__device__ int    g_boff[256];
__device__ int    g_csr[N_EDGES];        // src ids grouped by dst
__device__ float4 g_xs[N_NODES * 32];    // x * norm[src]  (fp32, for gather)
__device__ float4 g_hs[N_NODES * 32];    // hx * norm[src]
__device__ __nv_bfloat16 g_Ahi[(size_t)N_NODES * KDIM];  // A=[x|px|hx|ph] hi
__device__ __nv_bfloat16 g_Alo[(size_t)N_NODES * KDIM];  // lo
__device__ __nv_bfloat16 g_Wb_hi[KDIM * JDIM];  // W^T [n=512][k=512] hi
__device__ __nv_bfloat16 g_Wb_lo[KDIM * JDIM];  // lo
__device__ float  g_G[(size_t)N_NODES * JDIM];  // GEMM output [N x 512]

// ---------------- helpers ----------------
__device__ __forceinline__ uint32_t smem_u32(const void* p) {
    uint32_t a;
    asm("{ .reg .u64 t; cvta.to.shared.u64 t, %1; cvt.u32.u64 %0, t; }" : "=r"(a) : "l"(p));
    return a;
}
#define SWZ128(off) ((off) ^ (((off) >> 3) & 0x70))

__device__ __forceinline__ void ldsm_x4(uint32_t addr, uint32_t& r0, uint32_t& r1,
                                        uint32_t& r2, uint32_t& r3) {
    asm volatile("ldmatrix.sync.aligned.m8n8.x4.shared.b16 {%0,%1,%2,%3}, [%4];"
                 : "=r"(r0), "=r"(r1), "=r"(r2), "=r"(r3) : "r"(addr));
}

__device__ __forceinline__ void mma_bf16(float& d0, float& d1, float& d2, float& d3,
                                         uint32_t a0, uint32_t a1, uint32_t a2, uint32_t a3,
                                         uint32_t b0, uint32_t b1) {
    asm volatile(
        "mma.sync.aligned.m16n8k16.row.col.f32.bf16.bf16.f32 "
        "{%0,%1,%2,%3}, {%4,%5,%6,%7}, {%8,%9}, {%0,%1,%2,%3};"
        : "+f"(d0), "+f"(d1), "+f"(d2), "+f"(d3)
        : "r"(a0), "r"(a1), "r"(a2), "r"(a3), "r"(b0), "r"(b1));
}

__device__ __forceinline__ void cp16(uint32_t dst, const void* src, int srcsize) {
    asm volatile("cp.async.cg.shared.global [%0], [%1], 16, %2;"
                 :: "r"(dst), "l"(src), "r"(srcsize) : "memory");
}
#define CP_COMMIT() asm volatile("cp.async.commit_group;" ::: "memory")
#define CP_WAIT1()  asm volatile("cp.async.wait_group 1;" ::: "memory")
#define CP_WAIT0()  asm volatile("cp.async.wait_group 0;" ::: "memory")

__device__ __forceinline__ void split2(float a, float b, uint32_t& hi, uint32_t& lo) {
    __nv_bfloat16 ah = __float2bfloat16(a), bh = __float2bfloat16(b);
    __nv_bfloat16 al = __float2bfloat16(a - __bfloat162float(ah));
    __nv_bfloat16 bl = __float2bfloat16(b - __bfloat162float(bh));
    hi = ((uint32_t)__bfloat16_as_ushort(bh) << 16) | (uint32_t)__bfloat16_as_ushort(ah);
    lo = ((uint32_t)__bfloat16_as_ushort(bl) << 16) | (uint32_t)__bfloat16_as_ushort(al);
}

// ---------------- CSR build ----------------
__global__ void k_zero_cnt() {
    int i = blockIdx.x * blockDim.x + threadIdx.x;
    if (i < N_NODES) g_cnt[i] = 0;
}

__global__ void k_deg_i(const int* __restrict__ ei) {
    int e = blockIdx.x * blockDim.x + threadIdx.x;
    if (e < N_EDGES) atomicAdd(&g_cnt[__ldg(&ei[N_EDGES + e])], 1);
}

__global__ void k_scan1() {  // grid 196, block 256: block sums
    __shared__ int sh[256];
    int i = blockIdx.x * 256 + threadIdx.x;
    int v = (i < N_NODES) ? g_cnt[i] : 0;
    sh[threadIdx.x] = v;
    __syncthreads();
    for (int o = 128; o > 0; o >>= 1) {
        if (threadIdx.x < o) sh[threadIdx.x] += sh[threadIdx.x + o];
        __syncthreads();
    }
    if (threadIdx.x == 0) g_bsum[blockIdx.x] = sh[0];
}

__global__ void k_scan2() {  // 1 block 256: exclusive scan of block sums
    __shared__ int sh[256];
    int tid = threadIdx.x;
    int v = (tid < 196) ? g_bsum[tid] : 0;
    sh[tid] = v;
    __syncthreads();
    for (int o = 1; o < 256; o <<= 1) {
        int t = (tid >= o) ? sh[tid - o] : 0;
        __syncthreads();
        sh[tid] += t;
        __syncthreads();
    }
    g_boff[tid] = sh[tid] - v;  // exclusive
}

__global__ void k_scan3() {  // grid 196: per-block exclusive scan + offset
    __shared__ int sh[256];
    int tid = threadIdx.x;
    int i = blockIdx.x * 256 + tid;
    int v = (i < N_NODES) ? g_cnt[i] : 0;
    sh[tid] = v;
    __syncthreads();
    for (int o = 1; o < 256; o <<= 1) {
        int t = (tid >= o) ? sh[tid - o] : 0;
        __syncthreads();
        sh[tid] += t;
        __syncthreads();
    }
    if (i < N_NODES) {
        int excl = sh[tid] - v + g_boff[blockIdx.x];
        g_ptr[i] = excl;
        g_cur[i] = excl;
    }
}

__global__ void k_fill(const int* __restrict__ ei) {
    int e = blockIdx.x * blockDim.x + threadIdx.x;
    if (e >= N_EDGES) return;
    int src = __ldg(&ei[e]);
    int dst = __ldg(&ei[N_EDGES + e]);
    int pos = atomicAdd(&g_cur[dst], 1);
    g_csr[pos] = src;
}

// ---------------- scale: xs/hs fp32 + A blocks 0 (x), 2 (hx) bf16 hi/lo ----------------
__global__ void k_scale(const float4* __restrict__ x4, const float4* __restrict__ h4) {
    int i = blockIdx.x * blockDim.x + threadIdx.x;  // over N*32 float4
    if (i >= N_NODES * 32) return;
    int n = i >> 5, c4 = i & 31;
    float nrm = rsqrtf(fmaxf((float)g_cnt[n], 1.0f));
    float4 xv = x4[i];
    float4 hv = h4[i];
    // raw x, hx into A (blocks 0 and 2)
    uint32_t h01, l01, h23, l23;
    split2(xv.x, xv.y, h01, l01);
    split2(xv.z, xv.w, h23, l23);
    size_t baseA = (size_t)n * KDIM + c4 * 4;
    *(uint2*)&g_Ahi[baseA] = make_uint2(h01, h23);
    *(uint2*)&g_Alo[baseA] = make_uint2(l01, l23);
    split2(hv.x, hv.y, h01, l01);
    split2(hv.z, hv.w, h23, l23);
    *(uint2*)&g_Ahi[baseA + 256] = make_uint2(h01, h23);
    *(uint2*)&g_Alo[baseA + 256] = make_uint2(l01, l23);
    // scaled copies for gather
    xv.x *= nrm; xv.y *= nrm; xv.z *= nrm; xv.w *= nrm;
    g_xs[i] = xv;
    hv.x *= nrm; hv.y *= nrm; hv.z *= nrm; hv.w *= nrm;
    g_hs[i] = hv;
}

// ---------------- gather: warp per dst node, writes A blocks 1 (px), 3 (ph) ----------------
__global__ __launch_bounds__(256) void k_gather() {
    int wid = threadIdx.x >> 5, lane = threadIdx.x & 31;
    int n = blockIdx.x * 8 + wid;
    if (n >= N_NODES) return;
    int start = g_ptr[n];
    int cnt = g_cnt[n];
    float4 ax = make_float4(0.f, 0.f, 0.f, 0.f);
    float4 ah = make_float4(0.f, 0.f, 0.f, 0.f);
    for (int j0 = 0; j0 < cnt; j0 += 32) {
        int my = j0 + lane;
        int s = (my < cnt) ? g_csr[start + my] : 0;
        int m = min(32, cnt - j0);
        for (int t = 0; t < m; t++) {
            int src = __shfl_sync(0xffffffffu, s, t);
            float4 vx = g_xs[src * 32 + lane];
            ax.x += vx.x; ax.y += vx.y; ax.z += vx.z; ax.w += vx.w;
            float4 vh = g_hs[src * 32 + lane];
            ah.x += vh.x; ah.y += vh.y; ah.z += vh.z; ah.w += vh.w;
        }
    }
    float nn = -rsqrtf(fmaxf((float)cnt, 1.0f));
    ax.x *= nn; ax.y *= nn; ax.z *= nn; ax.w *= nn;
    ah.x *= nn; ah.y *= nn; ah.z *= nn; ah.w *= nn;
    uint32_t h01, l01, h23, l23;
    size_t baseA = (size_t)n * KDIM + lane * 4;
    split2(ax.x, ax.y, h01, l01);
    split2(ax.z, ax.w, h23, l23);
    *(uint2*)&g_Ahi[baseA + 128] = make_uint2(h01, h23);
    *(uint2*)&g_Alo[baseA + 128] = make_uint2(l01, l23);
    split2(ah.x, ah.y, h01, l01);
    split2(ah.z, ah.w, h23, l23);
    *(uint2*)&g_Ahi[baseA + 384] = make_uint2(h01, h23);
    *(uint2*)&g_Alo[baseA + 384] = make_uint2(l01, l23);
}

// ---------------- W^T concat, bf16 hi/lo ----------------
__global__ void k_wcat(const float* __restrict__ W_rx, const float* __restrict__ W_rh,
                       const float* __restrict__ W_ux, const float* __restrict__ W_uh,
                       const float* __restrict__ W_cx, const float* __restrict__ W_ch) {
    int idx = blockIdx.x * blockDim.x + threadIdx.x;
    if (idx >= KDIM * JDIM) return;
    int n = idx >> 9, k = idx & 511;
    int kb = k >> 7, jb = n >> 7;
    int f = k & 127, h = n & 127;
    const float* src = nullptr;
    if (jb == 0)      src = (kb < 2) ? W_rx : W_rh;
    else if (jb == 1) src = (kb < 2) ? W_ux : W_uh;
    else if (jb == 2) src = (kb < 2) ? W_cx : nullptr;
    else              src = (kb >= 2) ? W_ch : nullptr;
    float v = src ? src[(kb & 1) * (FDIM * FDIM) + f * FDIM + h] : 0.f;
    __nv_bfloat16 hi = __float2bfloat16(v);
    __nv_bfloat16 lo = __float2bfloat16(v - __bfloat162float(hi));
    g_Wb_hi[idx] = hi;
    g_Wb_lo[idx] = lo;
}

// ---------------- HMMA GEMM, double-buffered cp.async ----------------
// G[128 x 128] per CTA; A bf16 hi/lo precomputed; grid(391, 4), 256 thr.
#define STG   65536
#define SA_HI 0
#define SA_LO 16384
#define SB_HI 32768
#define SB_LO 49152
#define SMEM_GEMM 131072

__global__ __launch_bounds__(256, 1) void k_gemm_mma() {
    extern __shared__ char smem[];
    uint32_t sb = smem_u32(smem);
    int tid = threadIdx.x, wid = tid >> 5, lane = tid & 31;
    int row0 = blockIdx.x * 128;
    int n0g = blockIdx.y * 128;
    int wm = (wid & 1) * 64;
    int wn = (wid >> 1) * 32;

    float d[4][4][4];
#pragma unroll
    for (int i = 0; i < 4; i++)
#pragma unroll
        for (int j = 0; j < 4; j++)
#pragma unroll
            for (int q = 0; q < 4; q++) d[i][j][q] = 0.f;

    int a_row = wm + (lane & 15);
    int a_kb  = (lane >> 4) * 16;
    int b_row = wn + (lane & 7) + ((lane >> 4) << 3);
    int b_kb  = ((lane >> 3) & 1) * 16;

    // per-thread load decomposition: chunk id = tid + it*256 over 1024 (128 rows x 8 chunks)
    const char* pAhi = (const char*)g_Ahi;
    const char* pAlo = (const char*)g_Alo;
    const char* pBhi = (const char*)g_Wb_hi;
    const char* pBlo = (const char*)g_Wb_lo;

    auto load_stage = [&](int s, int buf) {
        uint32_t base = sb + buf * STG;
#pragma unroll
        for (int it = 0; it < 4; it++) {
            int id = tid + it * 256;
            int r = id >> 3, c = id & 7;
            uint32_t off = SWZ128((uint32_t)(r * 128 + c * 16));
            // A
            int row = row0 + r;
            long ga = ((long)row * KDIM + s * 64) * 2 + c * 16;
            int vsz = (row < N_NODES) ? 16 : 0;
            cp16(base + SA_HI + off, pAhi + ga, vsz);
            cp16(base + SA_LO + off, pAlo + ga, vsz);
            // B
            long gb = ((long)(n0g + r) * KDIM + s * 64) * 2 + c * 16;
            cp16(base + SB_HI + off, pBhi + gb, 16);
            cp16(base + SB_LO + off, pBlo + gb, 16);
        }
    };

    load_stage(0, 0);
    CP_COMMIT();

#pragma unroll 1
    for (int s = 0; s < 8; s++) {
        int buf = s & 1;
        if (s + 1 < 8) {
            load_stage(s + 1, buf ^ 1);
            CP_COMMIT();
            CP_WAIT1();
        } else {
            CP_WAIT0();
        }
        __syncthreads();

        uint32_t base = sb + buf * STG;
#pragma unroll
        for (int kk = 0; kk < 4; kk++) {
            uint32_t ahf[4][4], alf[4][4];
#pragma unroll
            for (int mf = 0; mf < 4; mf++) {
                uint32_t boff = SWZ128((uint32_t)((a_row + mf * 16) * 128 + kk * 32 + a_kb));
                ldsm_x4(base + SA_HI + boff, ahf[mf][0], ahf[mf][1], ahf[mf][2], ahf[mf][3]);
                ldsm_x4(base + SA_LO + boff, alf[mf][0], alf[mf][1], alf[mf][2], alf[mf][3]);
            }
            uint32_t bhf[4][2], blf[4][2];
#pragma unroll
            for (int pf = 0; pf < 2; pf++) {
                uint32_t boff = SWZ128((uint32_t)((b_row + pf * 16) * 128 + kk * 32 + b_kb));
                ldsm_x4(base + SB_HI + boff, bhf[2*pf][0], bhf[2*pf][1], bhf[2*pf+1][0], bhf[2*pf+1][1]);
                ldsm_x4(base + SB_LO + boff, blf[2*pf][0], blf[2*pf][1], blf[2*pf+1][0], blf[2*pf+1][1]);
            }
#pragma unroll
            for (int mf = 0; mf < 4; mf++)
#pragma unroll
                for (int nf = 0; nf < 4; nf++) {
                    float* dd = d[mf][nf];
                    mma_bf16(dd[0], dd[1], dd[2], dd[3],
                             ahf[mf][0], ahf[mf][1], ahf[mf][2], ahf[mf][3],
                             bhf[nf][0], bhf[nf][1]);
                    mma_bf16(dd[0], dd[1], dd[2], dd[3],
                             alf[mf][0], alf[mf][1], alf[mf][2], alf[mf][3],
                             bhf[nf][0], bhf[nf][1]);
                    mma_bf16(dd[0], dd[1], dd[2], dd[3],
                             ahf[mf][0], ahf[mf][1], ahf[mf][2], ahf[mf][3],
                             blf[nf][0], blf[nf][1]);
                }
        }
        __syncthreads();
    }

#pragma unroll
    for (int mf = 0; mf < 4; mf++) {
        int r0 = row0 + wm + mf * 16 + (lane >> 2);
        int c0 = n0g + wn + (lane & 3) * 2;
#pragma unroll
        for (int nf = 0; nf < 4; nf++) {
            float* dd = d[mf][nf];
            int c = c0 + nf * 8;
            if (r0 < N_NODES)
                *(float2*)&g_G[(size_t)r0 * JDIM + c] = make_float2(dd[0], dd[1]);
            if (r0 + 8 < N_NODES)
                *(float2*)&g_G[(size_t)(r0 + 8) * JDIM + c] = make_float2(dd[2], dd[3]);
        }
    }
}

__device__ __forceinline__ float sigm(float z) { return 1.0f / (1.0f + expf(-z)); }

__global__ void k_epilogue(const float* __restrict__ hx,
                           const float* __restrict__ b_rx, const float* __restrict__ b_rh,
                           const float* __restrict__ b_ux, const float* __restrict__ b_uh,
                           const float* __restrict__ b_cx, const float* __restrict__ b_ch,
                           float* __restrict__ out) {
    int idx = blockIdx.x * blockDim.x + threadIdx.x;
    if (idx >= N_NODES * FDIM) return;
    int n = idx >> 7, h = idx & 127;
    const float* g = &g_G[(size_t)n * JDIM];
    float R  = g[h];
    float U  = g[128 + h];
    float Cx = g[256 + h];
    float Ch = g[384 + h];
    float r = sigm(R + b_rx[h] + b_rh[h]);
    float u = sigm(U + b_ux[h] + b_uh[h]);
    float c = sigm(Cx + b_cx[h] + (Ch + b_ch[h]) * r);
    out[idx] = u * hx[idx] + (1.0f - u) * c;
}

// ---------------- launch ----------------
extern "C" void kernel_launch(void* const* d_in, const int* in_sizes, int n_in,
                              void* d_out, int out_size) {
    const int*   ei   = (const int*)d_in[0];
    const float* x    = (const float*)d_in[1];
    const float* hx   = (const float*)d_in[2];
    const float* W_rx = (const float*)d_in[3];
    const float* b_rx = (const float*)d_in[4];
    const float* W_rh = (const float*)d_in[5];
    const float* b_rh = (const float*)d_in[6];
    const float* W_ux = (const float*)d_in[7];
    const float* b_ux = (const float*)d_in[8];
    const float* W_uh = (const float*)d_in[9];
    const float* b_uh = (const float*)d_in[10];
    const float* W_cx = (const float*)d_in[11];
    const float* b_cx = (const float*)d_in[12];
    const float* W_ch = (const float*)d_in[13];
    const float* b_ch = (const float*)d_in[14];
    float* out = (float*)d_out;

    cudaFuncSetAttribute(k_gemm_mma, cudaFuncAttributeMaxDynamicSharedMemorySize, SMEM_GEMM);

    // CSR build
    k_zero_cnt<<<(N_NODES + 255) / 256, 256>>>();
    k_deg_i<<<(N_EDGES + 255) / 256, 256>>>(ei);
    k_scan1<<<196, 256>>>();
    k_scan2<<<1, 256>>>();
    k_scan3<<<196, 256>>>();
    k_fill<<<(N_EDGES + 255) / 256, 256>>>(ei);
    // node prep
    k_scale<<<(N_NODES * 32 + 255) / 256, 256>>>((const float4*)x, (const float4*)hx);
    // aggregation (gather)
    k_gather<<<(N_NODES + 7) / 8, 256>>>();
    // weights
    k_wcat<<<(KDIM * JDIM + 255) / 256, 256>>>(W_rx, W_rh, W_ux, W_uh, W_cx, W_ch);
    // GEMM
    {
        dim3 grid((N_NODES + 127) / 128, 4);
        k_gemm_mma<<<grid, 256, SMEM_GEMM>>>();
    }
    // fused gates + GRU update
    k_epilogue<<<(N_NODES * FDIM + 255) / 256, 256>>>(hx, b_rx, b_rh, b_ux, b_uh,
                                                      b_cx, b_ch, out);
}

// round 6
// speedup vs baseline: 3.2254x; 1.2472x over previous
#include <cuda_runtime.h>
#include <cuda_bf16.h>
#include <cuda_fp16.h>
#include <math.h>
#include <stdint.h>

#define N_NODES 50000
#define N_EDGES 1600000
#define FDIM 128
#define KDIM 512
#define JDIM 512

// ---------------- device scratch (no allocations allowed) ----------------
__device__ int    g_cnt[N_NODES];        // in-degree (int)
__device__ int    g_ptr[N_NODES];        // CSR row starts (exclusive scan)
__device__ int    g_cur[N_NODES];        // fill cursors
__device__ int    g_bsum[256];
__device__ int    g_boff[256];
__device__ int    g_csr[N_EDGES];        // src ids grouped by dst
__device__ uint4  g_msg[N_NODES * 32];   // packed fp16: {x*norm (4h), hx*norm (4h)} per lane
__device__ __nv_bfloat16 g_Ahi[(size_t)N_NODES * KDIM];  // A=[x|px|hx|ph] hi
__device__ __nv_bfloat16 g_Alo[(size_t)N_NODES * KDIM];  // lo
__device__ __nv_bfloat16 g_Wb_hi[KDIM * JDIM];  // W^T [n=512][k=512] hi
__device__ __nv_bfloat16 g_Wb_lo[KDIM * JDIM];  // lo
__device__ float  g_G[(size_t)N_NODES * JDIM];  // GEMM output [N x 512]

// ---------------- helpers ----------------
__device__ __forceinline__ uint32_t smem_u32(const void* p) {
    uint32_t a;
    asm("{ .reg .u64 t; cvta.to.shared.u64 t, %1; cvt.u32.u64 %0, t; }" : "=r"(a) : "l"(p));
    return a;
}
#define SWZ128(off) ((off) ^ (((off) >> 3) & 0x70))

__device__ __forceinline__ void ldsm_x4(uint32_t addr, uint32_t& r0, uint32_t& r1,
                                        uint32_t& r2, uint32_t& r3) {
    asm volatile("ldmatrix.sync.aligned.m8n8.x4.shared.b16 {%0,%1,%2,%3}, [%4];"
                 : "=r"(r0), "=r"(r1), "=r"(r2), "=r"(r3) : "r"(addr));
}

__device__ __forceinline__ void mma_bf16(float& d0, float& d1, float& d2, float& d3,
                                         uint32_t a0, uint32_t a1, uint32_t a2, uint32_t a3,
                                         uint32_t b0, uint32_t b1) {
    asm volatile(
        "mma.sync.aligned.m16n8k16.row.col.f32.bf16.bf16.f32 "
        "{%0,%1,%2,%3}, {%4,%5,%6,%7}, {%8,%9}, {%0,%1,%2,%3};"
        : "+f"(d0), "+f"(d1), "+f"(d2), "+f"(d3)
        : "r"(a0), "r"(a1), "r"(a2), "r"(a3), "r"(b0), "r"(b1));
}

__device__ __forceinline__ void cp16(uint32_t dst, const void* src, int srcsize) {
    asm volatile("cp.async.cg.shared.global [%0], [%1], 16, %2;"
                 :: "r"(dst), "l"(src), "r"(srcsize) : "memory");
}
#define CP_COMMIT() asm volatile("cp.async.commit_group;" ::: "memory")
#define CP_WAIT1()  asm volatile("cp.async.wait_group 1;" ::: "memory")
#define CP_WAIT0()  asm volatile("cp.async.wait_group 0;" ::: "memory")

__device__ __forceinline__ void split2(float a, float b, uint32_t& hi, uint32_t& lo) {
    __nv_bfloat16 ah = __float2bfloat16(a), bh = __float2bfloat16(b);
    __nv_bfloat16 al = __float2bfloat16(a - __bfloat162float(ah));
    __nv_bfloat16 bl = __float2bfloat16(b - __bfloat162float(bh));
    hi = ((uint32_t)__bfloat16_as_ushort(bh) << 16) | (uint32_t)__bfloat16_as_ushort(ah);
    lo = ((uint32_t)__bfloat16_as_ushort(bl) << 16) | (uint32_t)__bfloat16_as_ushort(al);
}

// ---------------- CSR build ----------------
__global__ void k_zero_cnt() {
    int i = blockIdx.x * blockDim.x + threadIdx.x;
    if (i < N_NODES) g_cnt[i] = 0;
}

__global__ void k_deg_i(const int* __restrict__ ei) {
    int e = blockIdx.x * blockDim.x + threadIdx.x;
    if (e < N_EDGES) atomicAdd(&g_cnt[__ldg(&ei[N_EDGES + e])], 1);
}

__global__ void k_scan1() {
    __shared__ int sh[256];
    int i = blockIdx.x * 256 + threadIdx.x;
    int v = (i < N_NODES) ? g_cnt[i] : 0;
    sh[threadIdx.x] = v;
    __syncthreads();
    for (int o = 128; o > 0; o >>= 1) {
        if (threadIdx.x < o) sh[threadIdx.x] += sh[threadIdx.x + o];
        __syncthreads();
    }
    if (threadIdx.x == 0) g_bsum[blockIdx.x] = sh[0];
}

__global__ void k_scan2() {
    __shared__ int sh[256];
    int tid = threadIdx.x;
    int v = (tid < 196) ? g_bsum[tid] : 0;
    sh[tid] = v;
    __syncthreads();
    for (int o = 1; o < 256; o <<= 1) {
        int t = (tid >= o) ? sh[tid - o] : 0;
        __syncthreads();
        sh[tid] += t;
        __syncthreads();
    }
    g_boff[tid] = sh[tid] - v;
}

__global__ void k_scan3() {
    __shared__ int sh[256];
    int tid = threadIdx.x;
    int i = blockIdx.x * 256 + tid;
    int v = (i < N_NODES) ? g_cnt[i] : 0;
    sh[tid] = v;
    __syncthreads();
    for (int o = 1; o < 256; o <<= 1) {
        int t = (tid >= o) ? sh[tid - o] : 0;
        __syncthreads();
        sh[tid] += t;
        __syncthreads();
    }
    if (i < N_NODES) {
        int excl = sh[tid] - v + g_boff[blockIdx.x];
        g_ptr[i] = excl;
        g_cur[i] = excl;
    }
}

__global__ void k_fill(const int* __restrict__ ei) {
    int e = blockIdx.x * blockDim.x + threadIdx.x;
    if (e >= N_EDGES) return;
    int src = __ldg(&ei[e]);
    int dst = __ldg(&ei[N_EDGES + e]);
    int pos = atomicAdd(&g_cur[dst], 1);
    g_csr[pos] = src;
}

// ---------------- scale: packed fp16 msg + A blocks 0 (x), 2 (hx) bf16 hi/lo ----------------
__global__ void k_scale(const float4* __restrict__ x4, const float4* __restrict__ h4) {
    int i = blockIdx.x * blockDim.x + threadIdx.x;  // over N*32 float4
    if (i >= N_NODES * 32) return;
    int n = i >> 5, c4 = i & 31;
    float nrm = rsqrtf(fmaxf((float)g_cnt[n], 1.0f));
    float4 xv = x4[i];
    float4 hv = h4[i];
    // raw x, hx into A (blocks 0 and 2)
    uint32_t h01, l01, h23, l23;
    split2(xv.x, xv.y, h01, l01);
    split2(xv.z, xv.w, h23, l23);
    size_t baseA = (size_t)n * KDIM + c4 * 4;
    *(uint2*)&g_Ahi[baseA] = make_uint2(h01, h23);
    *(uint2*)&g_Alo[baseA] = make_uint2(l01, l23);
    split2(hv.x, hv.y, h01, l01);
    split2(hv.z, hv.w, h23, l23);
    *(uint2*)&g_Ahi[baseA + 256] = make_uint2(h01, h23);
    *(uint2*)&g_Alo[baseA + 256] = make_uint2(l01, l23);
    // packed fp16 messages: {x*nrm (4 half), hx*nrm (4 half)}
    half2 x01 = __floats2half2_rn(xv.x * nrm, xv.y * nrm);
    half2 x23 = __floats2half2_rn(xv.z * nrm, xv.w * nrm);
    half2 hx01 = __floats2half2_rn(hv.x * nrm, hv.y * nrm);
    half2 hx23 = __floats2half2_rn(hv.z * nrm, hv.w * nrm);
    uint4 m;
    m.x = *(uint32_t*)&x01;  m.y = *(uint32_t*)&x23;
    m.z = *(uint32_t*)&hx01; m.w = *(uint32_t*)&hx23;
    g_msg[n * 32 + c4] = m;
}

// ---------------- gather: warp per dst node, writes A blocks 1 (px), 3 (ph) ----------------
__global__ __launch_bounds__(256) void k_gather() {
    int wid = threadIdx.x >> 5, lane = threadIdx.x & 31;
    int n = blockIdx.x * 8 + wid;
    if (n >= N_NODES) return;
    int start = g_ptr[n];
    int cnt = g_cnt[n];
    float4 ax = make_float4(0.f, 0.f, 0.f, 0.f);
    float4 ah = make_float4(0.f, 0.f, 0.f, 0.f);
    for (int j0 = 0; j0 < cnt; j0 += 32) {
        int my = j0 + lane;
        int s = (my < cnt) ? g_csr[start + my] : 0;
        int m = min(32, cnt - j0);
        for (int t = 0; t < m; t++) {
            int src = __shfl_sync(0xffffffffu, s, t);
            uint4 mm = g_msg[src * 32 + lane];
            float2 f0 = __half22float2(*(half2*)&mm.x);
            float2 f1 = __half22float2(*(half2*)&mm.y);
            float2 f2 = __half22float2(*(half2*)&mm.z);
            float2 f3 = __half22float2(*(half2*)&mm.w);
            ax.x += f0.x; ax.y += f0.y; ax.z += f1.x; ax.w += f1.y;
            ah.x += f2.x; ah.y += f2.y; ah.z += f3.x; ah.w += f3.y;
        }
    }
    float nn = -rsqrtf(fmaxf((float)cnt, 1.0f));
    ax.x *= nn; ax.y *= nn; ax.z *= nn; ax.w *= nn;
    ah.x *= nn; ah.y *= nn; ah.z *= nn; ah.w *= nn;
    uint32_t h01, l01, h23, l23;
    size_t baseA = (size_t)n * KDIM + lane * 4;
    split2(ax.x, ax.y, h01, l01);
    split2(ax.z, ax.w, h23, l23);
    *(uint2*)&g_Ahi[baseA + 128] = make_uint2(h01, h23);
    *(uint2*)&g_Alo[baseA + 128] = make_uint2(l01, l23);
    split2(ah.x, ah.y, h01, l01);
    split2(ah.z, ah.w, h23, l23);
    *(uint2*)&g_Ahi[baseA + 384] = make_uint2(h01, h23);
    *(uint2*)&g_Alo[baseA + 384] = make_uint2(l01, l23);
}

// ---------------- W^T concat, bf16 hi/lo ----------------
__global__ void k_wcat(const float* __restrict__ W_rx, const float* __restrict__ W_rh,
                       const float* __restrict__ W_ux, const float* __restrict__ W_uh,
                       const float* __restrict__ W_cx, const float* __restrict__ W_ch) {
    int idx = blockIdx.x * blockDim.x + threadIdx.x;
    if (idx >= KDIM * JDIM) return;
    int n = idx >> 9, k = idx & 511;
    int kb = k >> 7, jb = n >> 7;
    int f = k & 127, h = n & 127;
    const float* src = nullptr;
    if (jb == 0)      src = (kb < 2) ? W_rx : W_rh;
    else if (jb == 1) src = (kb < 2) ? W_ux : W_uh;
    else if (jb == 2) src = (kb < 2) ? W_cx : nullptr;
    else              src = (kb >= 2) ? W_ch : nullptr;
    float v = src ? src[(kb & 1) * (FDIM * FDIM) + f * FDIM + h] : 0.f;
    __nv_bfloat16 hi = __float2bfloat16(v);
    __nv_bfloat16 lo = __float2bfloat16(v - __bfloat162float(hi));
    g_Wb_hi[idx] = hi;
    g_Wb_lo[idx] = lo;
}

// ---------------- HMMA GEMM, double-buffered cp.async, zero-block skip ----------------
#define STG   65536
#define SA_HI 0
#define SA_LO 16384
#define SB_HI 32768
#define SB_LO 49152
#define SMEM_GEMM 131072

__global__ __launch_bounds__(256, 1) void k_gemm_mma() {
    extern __shared__ char smem[];
    uint32_t sb = smem_u32(smem);
    int tid = threadIdx.x, wid = tid >> 5, lane = tid & 31;
    int row0 = blockIdx.x * 128;
    int n0g = blockIdx.y * 128;
    int wm = (wid & 1) * 64;
    int wn = (wid >> 1) * 32;

    // zero-block skip: y==2 (Cx) uses K-blocks [0,256) only; y==3 (Ch) uses [256,512)
    int s_beg = (blockIdx.y == 3) ? 4 : 0;
    int s_end = (blockIdx.y == 2) ? 4 : 8;

    float d[4][4][4];
#pragma unroll
    for (int i = 0; i < 4; i++)
#pragma unroll
        for (int j = 0; j < 4; j++)
#pragma unroll
            for (int q = 0; q < 4; q++) d[i][j][q] = 0.f;

    int a_row = wm + (lane & 15);
    int a_kb  = (lane >> 4) * 16;
    int b_row = wn + (lane & 7) + ((lane >> 4) << 3);
    int b_kb  = ((lane >> 3) & 1) * 16;

    const char* pAhi = (const char*)g_Ahi;
    const char* pAlo = (const char*)g_Alo;
    const char* pBhi = (const char*)g_Wb_hi;
    const char* pBlo = (const char*)g_Wb_lo;

    auto load_stage = [&](int s, int buf) {
        uint32_t base = sb + buf * STG;
#pragma unroll
        for (int it = 0; it < 4; it++) {
            int id = tid + it * 256;
            int r = id >> 3, c = id & 7;
            uint32_t off = SWZ128((uint32_t)(r * 128 + c * 16));
            int row = row0 + r;
            long ga = ((long)row * KDIM + s * 64) * 2 + c * 16;
            int vsz = (row < N_NODES) ? 16 : 0;
            cp16(base + SA_HI + off, pAhi + ga, vsz);
            cp16(base + SA_LO + off, pAlo + ga, vsz);
            long gb = ((long)(n0g + r) * KDIM + s * 64) * 2 + c * 16;
            cp16(base + SB_HI + off, pBhi + gb, 16);
            cp16(base + SB_LO + off, pBlo + gb, 16);
        }
    };

    load_stage(s_beg, 0);
    CP_COMMIT();

#pragma unroll 1
    for (int s = s_beg; s < s_end; s++) {
        int buf = (s - s_beg) & 1;
        if (s + 1 < s_end) {
            load_stage(s + 1, buf ^ 1);
            CP_COMMIT();
            CP_WAIT1();
        } else {
            CP_WAIT0();
        }
        __syncthreads();

        uint32_t base = sb + buf * STG;
#pragma unroll
        for (int kk = 0; kk < 4; kk++) {
            uint32_t ahf[4][4], alf[4][4];
#pragma unroll
            for (int mf = 0; mf < 4; mf++) {
                uint32_t boff = SWZ128((uint32_t)((a_row + mf * 16) * 128 + kk * 32 + a_kb));
                ldsm_x4(base + SA_HI + boff, ahf[mf][0], ahf[mf][1], ahf[mf][2], ahf[mf][3]);
                ldsm_x4(base + SA_LO + boff, alf[mf][0], alf[mf][1], alf[mf][2], alf[mf][3]);
            }
            uint32_t bhf[4][2], blf[4][2];
#pragma unroll
            for (int pf = 0; pf < 2; pf++) {
                uint32_t boff = SWZ128((uint32_t)((b_row + pf * 16) * 128 + kk * 32 + b_kb));
                ldsm_x4(base + SB_HI + boff, bhf[2*pf][0], bhf[2*pf][1], bhf[2*pf+1][0], bhf[2*pf+1][1]);
                ldsm_x4(base + SB_LO + boff, blf[2*pf][0], blf[2*pf][1], blf[2*pf+1][0], blf[2*pf+1][1]);
            }
#pragma unroll
            for (int mf = 0; mf < 4; mf++)
#pragma unroll
                for (int nf = 0; nf < 4; nf++) {
                    float* dd = d[mf][nf];
                    mma_bf16(dd[0], dd[1], dd[2], dd[3],
                             ahf[mf][0], ahf[mf][1], ahf[mf][2], ahf[mf][3],
                             bhf[nf][0], bhf[nf][1]);
                    mma_bf16(dd[0], dd[1], dd[2], dd[3],
                             alf[mf][0], alf[mf][1], alf[mf][2], alf[mf][3],
                             bhf[nf][0], bhf[nf][1]);
                    mma_bf16(dd[0], dd[1], dd[2], dd[3],
                             ahf[mf][0], ahf[mf][1], ahf[mf][2], ahf[mf][3],
                             blf[nf][0], blf[nf][1]);
                }
        }
        __syncthreads();
    }

#pragma unroll
    for (int mf = 0; mf < 4; mf++) {
        int r0 = row0 + wm + mf * 16 + (lane >> 2);
        int c0 = n0g + wn + (lane & 3) * 2;
#pragma unroll
        for (int nf = 0; nf < 4; nf++) {
            float* dd = d[mf][nf];
            int c = c0 + nf * 8;
            if (r0 < N_NODES)
                *(float2*)&g_G[(size_t)r0 * JDIM + c] = make_float2(dd[0], dd[1]);
            if (r0 + 8 < N_NODES)
                *(float2*)&g_G[(size_t)(r0 + 8) * JDIM + c] = make_float2(dd[2], dd[3]);
        }
    }
}

__device__ __forceinline__ float sigm(float z) { return 1.0f / (1.0f + expf(-z)); }

__global__ void k_epilogue(const float* __restrict__ hx,
                           const float* __restrict__ b_rx, const float* __restrict__ b_rh,
                           const float* __restrict__ b_ux, const float* __restrict__ b_uh,
                           const float* __restrict__ b_cx, const float* __restrict__ b_ch,
                           float* __restrict__ out) {
    int idx = blockIdx.x * blockDim.x + threadIdx.x;
    if (idx >= N_NODES * FDIM) return;
    int n = idx >> 7, h = idx & 127;
    const float* g = &g_G[(size_t)n * JDIM];
    float R  = g[h];
    float U  = g[128 + h];
    float Cx = g[256 + h];
    float Ch = g[384 + h];
    float r = sigm(R + b_rx[h] + b_rh[h]);
    float u = sigm(U + b_ux[h] + b_uh[h]);
    float c = sigm(Cx + b_cx[h] + (Ch + b_ch[h]) * r);
    out[idx] = u * hx[idx] + (1.0f - u) * c;
}

// ---------------- launch ----------------
extern "C" void kernel_launch(void* const* d_in, const int* in_sizes, int n_in,
                              void* d_out, int out_size) {
    const int*   ei   = (const int*)d_in[0];
    const float* x    = (const float*)d_in[1];
    const float* hx   = (const float*)d_in[2];
    const float* W_rx = (const float*)d_in[3];
    const float* b_rx = (const float*)d_in[4];
    const float* W_rh = (const float*)d_in[5];
    const float* b_rh = (const float*)d_in[6];
    const float* W_ux = (const float*)d_in[7];
    const float* b_ux = (const float*)d_in[8];
    const float* W_uh = (const float*)d_in[9];
    const float* b_uh = (const float*)d_in[10];
    const float* W_cx = (const float*)d_in[11];
    const float* b_cx = (const float*)d_in[12];
    const float* W_ch = (const float*)d_in[13];
    const float* b_ch = (const float*)d_in[14];
    float* out = (float*)d_out;

    cudaFuncSetAttribute(k_gemm_mma, cudaFuncAttributeMaxDynamicSharedMemorySize, SMEM_GEMM);

    // CSR build
    k_zero_cnt<<<(N_NODES + 255) / 256, 256>>>();
    k_deg_i<<<(N_EDGES + 255) / 256, 256>>>(ei);
    k_scan1<<<196, 256>>>();
    k_scan2<<<1, 256>>>();
    k_scan3<<<196, 256>>>();
    k_fill<<<(N_EDGES + 255) / 256, 256>>>(ei);
    // node prep
    k_scale<<<(N_NODES * 32 + 255) / 256, 256>>>((const float4*)x, (const float4*)hx);
    // aggregation (gather)
    k_gather<<<(N_NODES + 7) / 8, 256>>>();
    // weights
    k_wcat<<<(KDIM * JDIM + 255) / 256, 256>>>(W_rx, W_rh, W_ux, W_uh, W_cx, W_ch);
    // GEMM
    {
        dim3 grid((N_NODES + 127) / 128, 4);
        k_gemm_mma<<<grid, 256, SMEM_GEMM>>>();
    }
    // fused gates + GRU update
    k_epilogue<<<(N_NODES * FDIM + 255) / 256, 256>>>(hx, b_rx, b_rh, b_ux, b_uh,
                                                      b_cx, b_ch, out);
}

// round 7
// speedup vs baseline: 3.7872x; 1.1742x over previous
#include <cuda_runtime.h>
#include <cuda_bf16.h>
#include <cuda_fp16.h>
#include <math.h>
#include <stdint.h>

#define N_NODES 50000
#define N_EDGES 1600000
#define FDIM 128
#define KDIM 512
#define JDIM 512

// ---------------- device scratch (no allocations allowed) ----------------
__device__ int    g_cnt[N_NODES];        // in-degree (int)
__device__ int    g_ptr[N_NODES];        // CSR row starts (exclusive scan)
__device__ int    g_cur[N_NODES];        // fill cursors
__device__ int    g_bsum[256];
__device__ int    g_boff[256];
__device__ int    g_csr[N_EDGES];        // src ids grouped by dst
__device__ uint4  g_msg[N_NODES * 32];   // packed fp16: {x*norm (4h), hx*norm (4h)} per lane
__device__ __half g_Ah[(size_t)N_NODES * KDIM];   // A=[x|px|hx|ph], fp16
__device__ __half g_Wh_hi[KDIM * JDIM];  // W^T [n=512][k=512] fp16 hi
__device__ __half g_Wh_lo[KDIM * JDIM];  // fp16 residual (subnormal-range ok)
__device__ float  g_G[(size_t)N_NODES * JDIM];  // GEMM output [N x 512]

// ---------------- helpers ----------------
__device__ __forceinline__ uint32_t smem_u32(const void* p) {
    uint32_t a;
    asm("{ .reg .u64 t; cvta.to.shared.u64 t, %1; cvt.u32.u64 %0, t; }" : "=r"(a) : "l"(p));
    return a;
}
#define SWZ128(off) ((off) ^ (((off) >> 3) & 0x70))

__device__ __forceinline__ void ldsm_x4(uint32_t addr, uint32_t& r0, uint32_t& r1,
                                        uint32_t& r2, uint32_t& r3) {
    asm volatile("ldmatrix.sync.aligned.m8n8.x4.shared.b16 {%0,%1,%2,%3}, [%4];"
                 : "=r"(r0), "=r"(r1), "=r"(r2), "=r"(r3) : "r"(addr));
}

__device__ __forceinline__ void mma_f16(float& d0, float& d1, float& d2, float& d3,
                                        uint32_t a0, uint32_t a1, uint32_t a2, uint32_t a3,
                                        uint32_t b0, uint32_t b1) {
    asm volatile(
        "mma.sync.aligned.m16n8k16.row.col.f32.f16.f16.f32 "
        "{%0,%1,%2,%3}, {%4,%5,%6,%7}, {%8,%9}, {%0,%1,%2,%3};"
        : "+f"(d0), "+f"(d1), "+f"(d2), "+f"(d3)
        : "r"(a0), "r"(a1), "r"(a2), "r"(a3), "r"(b0), "r"(b1));
}

__device__ __forceinline__ void cp16(uint32_t dst, const void* src, int srcsize) {
    asm volatile("cp.async.cg.shared.global [%0], [%1], 16, %2;"
                 :: "r"(dst), "l"(src), "r"(srcsize) : "memory");
}
#define CP_COMMIT() asm volatile("cp.async.commit_group;" ::: "memory")
#define CP_WAIT1()  asm volatile("cp.async.wait_group 1;" ::: "memory")
#define CP_WAIT0()  asm volatile("cp.async.wait_group 0;" ::: "memory")

// ---------------- CSR build ----------------
__global__ void k_zero_cnt() {
    int i = blockIdx.x * blockDim.x + threadIdx.x;
    if (i < N_NODES) g_cnt[i] = 0;
}

__global__ void k_deg_i(const int* __restrict__ ei) {
    int e = blockIdx.x * blockDim.x + threadIdx.x;
    if (e < N_EDGES) atomicAdd(&g_cnt[__ldg(&ei[N_EDGES + e])], 1);
}

__global__ void k_scan1() {
    __shared__ int sh[256];
    int i = blockIdx.x * 256 + threadIdx.x;
    int v = (i < N_NODES) ? g_cnt[i] : 0;
    sh[threadIdx.x] = v;
    __syncthreads();
    for (int o = 128; o > 0; o >>= 1) {
        if (threadIdx.x < o) sh[threadIdx.x] += sh[threadIdx.x + o];
        __syncthreads();
    }
    if (threadIdx.x == 0) g_bsum[blockIdx.x] = sh[0];
}

__global__ void k_scan2() {
    __shared__ int sh[256];
    int tid = threadIdx.x;
    int v = (tid < 196) ? g_bsum[tid] : 0;
    sh[tid] = v;
    __syncthreads();
    for (int o = 1; o < 256; o <<= 1) {
        int t = (tid >= o) ? sh[tid - o] : 0;
        __syncthreads();
        sh[tid] += t;
        __syncthreads();
    }
    g_boff[tid] = sh[tid] - v;
}

__global__ void k_scan3() {
    __shared__ int sh[256];
    int tid = threadIdx.x;
    int i = blockIdx.x * 256 + tid;
    int v = (i < N_NODES) ? g_cnt[i] : 0;
    sh[tid] = v;
    __syncthreads();
    for (int o = 1; o < 256; o <<= 1) {
        int t = (tid >= o) ? sh[tid - o] : 0;
        __syncthreads();
        sh[tid] += t;
        __syncthreads();
    }
    if (i < N_NODES) {
        int excl = sh[tid] - v + g_boff[blockIdx.x];
        g_ptr[i] = excl;
        g_cur[i] = excl;
    }
}

__global__ void k_fill(const int* __restrict__ ei) {
    int e = blockIdx.x * blockDim.x + threadIdx.x;
    if (e >= N_EDGES) return;
    int src = __ldg(&ei[e]);
    int dst = __ldg(&ei[N_EDGES + e]);
    int pos = atomicAdd(&g_cur[dst], 1);
    g_csr[pos] = src;
}

// ---------------- scale: packed fp16 msg + A blocks 0 (x), 2 (hx) fp16 ----------------
__global__ void k_scale(const float4* __restrict__ x4, const float4* __restrict__ h4) {
    int i = blockIdx.x * blockDim.x + threadIdx.x;  // over N*32 float4
    if (i >= N_NODES * 32) return;
    int n = i >> 5, c4 = i & 31;
    float nrm = rsqrtf(fmaxf((float)g_cnt[n], 1.0f));
    float4 xv = x4[i];
    float4 hv = h4[i];
    // raw x, hx into A (blocks 0 and 2) as fp16
    half2 xa = __floats2half2_rn(xv.x, xv.y);
    half2 xb = __floats2half2_rn(xv.z, xv.w);
    half2 ha = __floats2half2_rn(hv.x, hv.y);
    half2 hb = __floats2half2_rn(hv.z, hv.w);
    size_t baseA = (size_t)n * KDIM + c4 * 4;
    *(uint2*)&g_Ah[baseA]       = make_uint2(*(uint32_t*)&xa, *(uint32_t*)&xb);
    *(uint2*)&g_Ah[baseA + 256] = make_uint2(*(uint32_t*)&ha, *(uint32_t*)&hb);
    // packed fp16 messages: {x*nrm (4 half), hx*nrm (4 half)}
    half2 x01 = __floats2half2_rn(xv.x * nrm, xv.y * nrm);
    half2 x23 = __floats2half2_rn(xv.z * nrm, xv.w * nrm);
    half2 hx01 = __floats2half2_rn(hv.x * nrm, hv.y * nrm);
    half2 hx23 = __floats2half2_rn(hv.z * nrm, hv.w * nrm);
    uint4 m;
    m.x = *(uint32_t*)&x01;  m.y = *(uint32_t*)&x23;
    m.z = *(uint32_t*)&hx01; m.w = *(uint32_t*)&hx23;
    g_msg[n * 32 + c4] = m;
}

// ---------------- gather: warp per dst node, writes A blocks 1 (px), 3 (ph) ----------------
__device__ __forceinline__ void acc_msg(uint4 mm, float4& ax, float4& ah) {
    float2 f0 = __half22float2(*(half2*)&mm.x);
    float2 f1 = __half22float2(*(half2*)&mm.y);
    float2 f2 = __half22float2(*(half2*)&mm.z);
    float2 f3 = __half22float2(*(half2*)&mm.w);
    ax.x += f0.x; ax.y += f0.y; ax.z += f1.x; ax.w += f1.y;
    ah.x += f2.x; ah.y += f2.y; ah.z += f3.x; ah.w += f3.y;
}

__global__ __launch_bounds__(256) void k_gather() {
    int wid = threadIdx.x >> 5, lane = threadIdx.x & 31;
    int n = blockIdx.x * 8 + wid;
    if (n >= N_NODES) return;
    int start = g_ptr[n];
    int cnt = g_cnt[n];
    float4 ax = make_float4(0.f, 0.f, 0.f, 0.f);
    float4 ah = make_float4(0.f, 0.f, 0.f, 0.f);
    for (int j0 = 0; j0 < cnt; j0 += 32) {
        int my = j0 + lane;
        int sreg = (my < cnt) ? g_csr[start + my] : 0;
        int m = min(32, cnt - j0);
        int t = 0;
        for (; t + 4 <= m; t += 4) {  // MLP=4: batch 4 independent row loads
            int s0 = __shfl_sync(0xffffffffu, sreg, t);
            int s1 = __shfl_sync(0xffffffffu, sreg, t + 1);
            int s2 = __shfl_sync(0xffffffffu, sreg, t + 2);
            int s3 = __shfl_sync(0xffffffffu, sreg, t + 3);
            uint4 m0 = g_msg[s0 * 32 + lane];
            uint4 m1 = g_msg[s1 * 32 + lane];
            uint4 m2 = g_msg[s2 * 32 + lane];
            uint4 m3 = g_msg[s3 * 32 + lane];
            acc_msg(m0, ax, ah);
            acc_msg(m1, ax, ah);
            acc_msg(m2, ax, ah);
            acc_msg(m3, ax, ah);
        }
        for (; t < m; t++) {
            int src = __shfl_sync(0xffffffffu, sreg, t);
            uint4 mm = g_msg[src * 32 + lane];
            acc_msg(mm, ax, ah);
        }
    }
    float nn = -rsqrtf(fmaxf((float)cnt, 1.0f));
    half2 pa = __floats2half2_rn(ax.x * nn, ax.y * nn);
    half2 pb = __floats2half2_rn(ax.z * nn, ax.w * nn);
    half2 qa = __floats2half2_rn(ah.x * nn, ah.y * nn);
    half2 qb = __floats2half2_rn(ah.z * nn, ah.w * nn);
    size_t baseA = (size_t)n * KDIM + lane * 4;
    *(uint2*)&g_Ah[baseA + 128] = make_uint2(*(uint32_t*)&pa, *(uint32_t*)&pb);
    *(uint2*)&g_Ah[baseA + 384] = make_uint2(*(uint32_t*)&qa, *(uint32_t*)&qb);
}

// ---------------- W^T concat, fp16 hi/lo ----------------
__global__ void k_wcat(const float* __restrict__ W_rx, const float* __restrict__ W_rh,
                       const float* __restrict__ W_ux, const float* __restrict__ W_uh,
                       const float* __restrict__ W_cx, const float* __restrict__ W_ch) {
    int idx = blockIdx.x * blockDim.x + threadIdx.x;
    if (idx >= KDIM * JDIM) return;
    int n = idx >> 9, k = idx & 511;
    int kb = k >> 7, jb = n >> 7;
    int f = k & 127, h = n & 127;
    const float* src = nullptr;
    if (jb == 0)      src = (kb < 2) ? W_rx : W_rh;
    else if (jb == 1) src = (kb < 2) ? W_ux : W_uh;
    else if (jb == 2) src = (kb < 2) ? W_cx : nullptr;
    else              src = (kb >= 2) ? W_ch : nullptr;
    float v = src ? src[(kb & 1) * (FDIM * FDIM) + f * FDIM + h] : 0.f;
    __half hi = __float2half_rn(v);
    __half lo = __float2half_rn(v - __half2float(hi));
    g_Wh_hi[idx] = hi;
    g_Wh_lo[idx] = lo;
}

// ---------------- HMMA GEMM (fp16 A single, W hi/lo), double-buffered ----------------
#define STG   49152
#define SA    0
#define SB_HI 16384
#define SB_LO 32768
#define SMEM_GEMM 98304

__global__ __launch_bounds__(256, 1) void k_gemm_mma() {
    extern __shared__ char smem[];
    uint32_t sb = smem_u32(smem);
    int tid = threadIdx.x, wid = tid >> 5, lane = tid & 31;
    int row0 = blockIdx.x * 128;
    int n0g = blockIdx.y * 128;
    int wm = (wid & 1) * 64;
    int wn = (wid >> 1) * 32;

    // zero-block skip: y==2 (Cx) uses K-blocks [0,256); y==3 (Ch) uses [256,512)
    int s_beg = (blockIdx.y == 3) ? 4 : 0;
    int s_end = (blockIdx.y == 2) ? 4 : 8;

    float d[4][4][4];
#pragma unroll
    for (int i = 0; i < 4; i++)
#pragma unroll
        for (int j = 0; j < 4; j++)
#pragma unroll
            for (int q = 0; q < 4; q++) d[i][j][q] = 0.f;

    int a_row = wm + (lane & 15);
    int a_kb  = (lane >> 4) * 16;
    int b_row = wn + (lane & 7) + ((lane >> 4) << 3);
    int b_kb  = ((lane >> 3) & 1) * 16;

    const char* pA   = (const char*)g_Ah;
    const char* pBhi = (const char*)g_Wh_hi;
    const char* pBlo = (const char*)g_Wh_lo;

    auto load_stage = [&](int s, int buf) {
        uint32_t base = sb + buf * STG;
#pragma unroll
        for (int it = 0; it < 4; it++) {
            int id = tid + it * 256;
            int r = id >> 3, c = id & 7;
            uint32_t off = SWZ128((uint32_t)(r * 128 + c * 16));
            int row = row0 + r;
            long ga = ((long)row * KDIM + s * 64) * 2 + c * 16;
            int vsz = (row < N_NODES) ? 16 : 0;
            cp16(base + SA + off, pA + ga, vsz);
            long gb = ((long)(n0g + r) * KDIM + s * 64) * 2 + c * 16;
            cp16(base + SB_HI + off, pBhi + gb, 16);
            cp16(base + SB_LO + off, pBlo + gb, 16);
        }
    };

    load_stage(s_beg, 0);
    CP_COMMIT();

#pragma unroll 1
    for (int s = s_beg; s < s_end; s++) {
        int buf = (s - s_beg) & 1;
        if (s + 1 < s_end) {
            load_stage(s + 1, buf ^ 1);
            CP_COMMIT();
            CP_WAIT1();
        } else {
            CP_WAIT0();
        }
        __syncthreads();

        uint32_t base = sb + buf * STG;
#pragma unroll
        for (int kk = 0; kk < 4; kk++) {
            uint32_t af[4][4];
#pragma unroll
            for (int mf = 0; mf < 4; mf++) {
                uint32_t boff = SWZ128((uint32_t)((a_row + mf * 16) * 128 + kk * 32 + a_kb));
                ldsm_x4(base + SA + boff, af[mf][0], af[mf][1], af[mf][2], af[mf][3]);
            }
            uint32_t bhf[4][2], blf[4][2];
#pragma unroll
            for (int pf = 0; pf < 2; pf++) {
                uint32_t boff = SWZ128((uint32_t)((b_row + pf * 16) * 128 + kk * 32 + b_kb));
                ldsm_x4(base + SB_HI + boff, bhf[2*pf][0], bhf[2*pf][1], bhf[2*pf+1][0], bhf[2*pf+1][1]);
                ldsm_x4(base + SB_LO + boff, blf[2*pf][0], blf[2*pf][1], blf[2*pf+1][0], blf[2*pf+1][1]);
            }
#pragma unroll
            for (int mf = 0; mf < 4; mf++)
#pragma unroll
                for (int nf = 0; nf < 4; nf++) {
                    float* dd = d[mf][nf];
                    mma_f16(dd[0], dd[1], dd[2], dd[3],
                            af[mf][0], af[mf][1], af[mf][2], af[mf][3],
                            bhf[nf][0], bhf[nf][1]);
                    mma_f16(dd[0], dd[1], dd[2], dd[3],
                            af[mf][0], af[mf][1], af[mf][2], af[mf][3],
                            blf[nf][0], blf[nf][1]);
                }
        }
        __syncthreads();
    }

#pragma unroll
    for (int mf = 0; mf < 4; mf++) {
        int r0 = row0 + wm + mf * 16 + (lane >> 2);
        int c0 = n0g + wn + (lane & 3) * 2;
#pragma unroll
        for (int nf = 0; nf < 4; nf++) {
            float* dd = d[mf][nf];
            int c = c0 + nf * 8;
            if (r0 < N_NODES)
                *(float2*)&g_G[(size_t)r0 * JDIM + c] = make_float2(dd[0], dd[1]);
            if (r0 + 8 < N_NODES)
                *(float2*)&g_G[(size_t)(r0 + 8) * JDIM + c] = make_float2(dd[2], dd[3]);
        }
    }
}

__device__ __forceinline__ float sigm(float z) { return 1.0f / (1.0f + expf(-z)); }

__global__ void k_epilogue(const float* __restrict__ hx,
                           const float* __restrict__ b_rx, const float* __restrict__ b_rh,
                           const float* __restrict__ b_ux, const float* __restrict__ b_uh,
                           const float* __restrict__ b_cx, const float* __restrict__ b_ch,
                           float* __restrict__ out) {
    int idx = blockIdx.x * blockDim.x + threadIdx.x;
    if (idx >= N_NODES * FDIM) return;
    int n = idx >> 7, h = idx & 127;
    const float* g = &g_G[(size_t)n * JDIM];
    float R  = g[h];
    float U  = g[128 + h];
    float Cx = g[256 + h];
    float Ch = g[384 + h];
    float r = sigm(R + b_rx[h] + b_rh[h]);
    float u = sigm(U + b_ux[h] + b_uh[h]);
    float c = sigm(Cx + b_cx[h] + (Ch + b_ch[h]) * r);
    out[idx] = u * hx[idx] + (1.0f - u) * c;
}

// ---------------- launch ----------------
extern "C" void kernel_launch(void* const* d_in, const int* in_sizes, int n_in,
                              void* d_out, int out_size) {
    const int*   ei   = (const int*)d_in[0];
    const float* x    = (const float*)d_in[1];
    const float* hx   = (const float*)d_in[2];
    const float* W_rx = (const float*)d_in[3];
    const float* b_rx = (const float*)d_in[4];
    const float* W_rh = (const float*)d_in[5];
    const float* b_rh = (const float*)d_in[6];
    const float* W_ux = (const float*)d_in[7];
    const float* b_ux = (const float*)d_in[8];
    const float* W_uh = (const float*)d_in[9];
    const float* b_uh = (const float*)d_in[10];
    const float* W_cx = (const float*)d_in[11];
    const float* b_cx = (const float*)d_in[12];
    const float* W_ch = (const float*)d_in[13];
    const float* b_ch = (const float*)d_in[14];
    float* out = (float*)d_out;

    cudaFuncSetAttribute(k_gemm_mma, cudaFuncAttributeMaxDynamicSharedMemorySize, SMEM_GEMM);

    // CSR build
    k_zero_cnt<<<(N_NODES + 255) / 256, 256>>>();
    k_deg_i<<<(N_EDGES + 255) / 256, 256>>>(ei);
    k_scan1<<<196, 256>>>();
    k_scan2<<<1, 256>>>();
    k_scan3<<<196, 256>>>();
    k_fill<<<(N_EDGES + 255) / 256, 256>>>(ei);
    // node prep
    k_scale<<<(N_NODES * 32 + 255) / 256, 256>>>((const float4*)x, (const float4*)hx);
    // aggregation (gather)
    k_gather<<<(N_NODES + 7) / 8, 256>>>();
    // weights
    k_wcat<<<(KDIM * JDIM + 255) / 256, 256>>>(W_rx, W_rh, W_ux, W_uh, W_cx, W_ch);
    // GEMM
    {
        dim3 grid((N_NODES + 127) / 128, 4);
        k_gemm_mma<<<grid, 256, SMEM_GEMM>>>();
    }
    // fused gates + GRU update
    k_epilogue<<<(N_NODES * FDIM + 255) / 256, 256>>>(hx, b_rx, b_rh, b_ux, b_uh,
                                                      b_cx, b_ch, out);
}

// round 9
// speedup vs baseline: 4.8378x; 1.2774x over previous
#include <cuda_runtime.h>
#include <cuda_fp16.h>
#include <math.h>
#include <stdint.h>

#define N_NODES 50000
#define N_EDGES 1600000
#define FDIM 128
#define KDIM 512
#define JDIM 512

// ---------------- device scratch (no allocations allowed) ----------------
__device__ int    g_cnt[N_NODES];        // in-degree (int)
__device__ int    g_ptr[N_NODES];        // CSR row starts
__device__ int    g_cur[N_NODES];        // fill cursors
__device__ int    g_total;               // atomic ticket for block offsets
__device__ int    g_csr[N_EDGES];        // src ids grouped by dst
__device__ uint4  g_msg[N_NODES * 32];   // packed fp16: {x*norm (4h), hx*norm (4h)} per lane
__device__ __half g_Ah[(size_t)N_NODES * KDIM];   // A=[x|px|hx|ph], fp16
__device__ __half g_Wh[KDIM * JDIM];     // W^T [n=512][k=512] fp16
__device__ float  g_G[(size_t)N_NODES * JDIM];  // GEMM output [N x 512]

// ---------------- helpers ----------------
__device__ __forceinline__ uint32_t smem_u32(const void* p) {
    uint32_t a;
    asm("{ .reg .u64 t; cvta.to.shared.u64 t, %1; cvt.u32.u64 %0, t; }" : "=r"(a) : "l"(p));
    return a;
}
#define SWZ128(off) ((off) ^ (((off) >> 3) & 0x70))

__device__ __forceinline__ void ldsm_x4(uint32_t addr, uint32_t& r0, uint32_t& r1,
                                        uint32_t& r2, uint32_t& r3) {
    asm volatile("ldmatrix.sync.aligned.m8n8.x4.shared.b16 {%0,%1,%2,%3}, [%4];"
                 : "=r"(r0), "=r"(r1), "=r"(r2), "=r"(r3) : "r"(addr));
}

__device__ __forceinline__ void mma_f16(float& d0, float& d1, float& d2, float& d3,
                                        uint32_t a0, uint32_t a1, uint32_t a2, uint32_t a3,
                                        uint32_t b0, uint32_t b1) {
    asm volatile(
        "mma.sync.aligned.m16n8k16.row.col.f32.f16.f16.f32 "
        "{%0,%1,%2,%3}, {%4,%5,%6,%7}, {%8,%9}, {%0,%1,%2,%3};"
        : "+f"(d0), "+f"(d1), "+f"(d2), "+f"(d3)
        : "r"(a0), "r"(a1), "r"(a2), "r"(a3), "r"(b0), "r"(b1));
}

__device__ __forceinline__ void cp16(uint32_t dst, const void* src, int srcsize) {
    asm volatile("cp.async.cg.shared.global [%0], [%1], 16, %2;"
                 :: "r"(dst), "l"(src), "r"(srcsize) : "memory");
}
#define CP_COMMIT() asm volatile("cp.async.commit_group;" ::: "memory")
#define CP_WAIT1()  asm volatile("cp.async.wait_group 1;" ::: "memory")
#define CP_WAIT0()  asm volatile("cp.async.wait_group 0;" ::: "memory")

// ---------------- CSR build ----------------
__global__ void k_zero_cnt() {
    int i = blockIdx.x * blockDim.x + threadIdx.x;
    if (i < N_NODES) g_cnt[i] = 0;
    if (i == 0) g_total = 0;
}

__global__ void k_deg_i(const int* __restrict__ ei) {
    int e = blockIdx.x * blockDim.x + threadIdx.x;
    if (e < N_EDGES) atomicAdd(&g_cnt[__ldg(&ei[N_EDGES + e])], 1);
}

// single-kernel scan: per-block inclusive scan + atomic ticket for block base.
// CSR slab order across blocks is arbitrary but self-consistent (ptr==cur seed).
__global__ void k_scan() {
    __shared__ int sh[256];
    __shared__ int base;
    int tid = threadIdx.x;
    int i = blockIdx.x * 256 + tid;
    int v = (i < N_NODES) ? g_cnt[i] : 0;
    sh[tid] = v;
    __syncthreads();
    for (int o = 1; o < 256; o <<= 1) {
        int t = (tid >= o) ? sh[tid - o] : 0;
        __syncthreads();
        sh[tid] += t;
        __syncthreads();
    }
    if (tid == 255) base = atomicAdd(&g_total, sh[255]);
    __syncthreads();
    if (i < N_NODES) {
        int excl = sh[tid] - v + base;
        g_ptr[i] = excl;
        g_cur[i] = excl;
    }
}

__global__ void k_fill(const int* __restrict__ ei) {
    int e = blockIdx.x * blockDim.x + threadIdx.x;
    if (e >= N_EDGES) return;
    int src = __ldg(&ei[e]);
    int dst = __ldg(&ei[N_EDGES + e]);
    int pos = atomicAdd(&g_cur[dst], 1);
    g_csr[pos] = src;
}

// ---------------- scale: packed fp16 msg + A blocks 0 (x), 2 (hx) fp16 ----------------
__global__ void k_scale(const float4* __restrict__ x4, const float4* __restrict__ h4) {
    int i = blockIdx.x * blockDim.x + threadIdx.x;  // over N*32 float4
    if (i >= N_NODES * 32) return;
    int n = i >> 5, c4 = i & 31;
    float nrm = rsqrtf(fmaxf((float)g_cnt[n], 1.0f));
    float4 xv = x4[i];
    float4 hv = h4[i];
    half2 xa = __floats2half2_rn(xv.x, xv.y);
    half2 xb = __floats2half2_rn(xv.z, xv.w);
    half2 ha = __floats2half2_rn(hv.x, hv.y);
    half2 hb = __floats2half2_rn(hv.z, hv.w);
    size_t baseA = (size_t)n * KDIM + c4 * 4;
    *(uint2*)&g_Ah[baseA]       = make_uint2(*(uint32_t*)&xa, *(uint32_t*)&xb);
    *(uint2*)&g_Ah[baseA + 256] = make_uint2(*(uint32_t*)&ha, *(uint32_t*)&hb);
    half2 x01 = __floats2half2_rn(xv.x * nrm, xv.y * nrm);
    half2 x23 = __floats2half2_rn(xv.z * nrm, xv.w * nrm);
    half2 hx01 = __floats2half2_rn(hv.x * nrm, hv.y * nrm);
    half2 hx23 = __floats2half2_rn(hv.z * nrm, hv.w * nrm);
    uint4 m;
    m.x = *(uint32_t*)&x01;  m.y = *(uint32_t*)&x23;
    m.z = *(uint32_t*)&hx01; m.w = *(uint32_t*)&hx23;
    g_msg[n * 32 + c4] = m;
}

// ---------------- gather: warp per dst node, writes A blocks 1 (px), 3 (ph) ----------------
__device__ __forceinline__ void acc_msg(uint4 mm, float4& ax, float4& ah) {
    float2 f0 = __half22float2(*(half2*)&mm.x);
    float2 f1 = __half22float2(*(half2*)&mm.y);
    float2 f2 = __half22float2(*(half2*)&mm.z);
    float2 f3 = __half22float2(*(half2*)&mm.w);
    ax.x += f0.x; ax.y += f0.y; ax.z += f1.x; ax.w += f1.y;
    ah.x += f2.x; ah.y += f2.y; ah.z += f3.x; ah.w += f3.y;
}

__global__ __launch_bounds__(256) void k_gather() {
    int wid = threadIdx.x >> 5, lane = threadIdx.x & 31;
    int n = blockIdx.x * 8 + wid;
    if (n >= N_NODES) return;
    int start = g_ptr[n];
    int cnt = g_cnt[n];
    float4 ax = make_float4(0.f, 0.f, 0.f, 0.f);
    float4 ah = make_float4(0.f, 0.f, 0.f, 0.f);
    for (int j0 = 0; j0 < cnt; j0 += 32) {
        int my = j0 + lane;
        int sreg = (my < cnt) ? g_csr[start + my] : 0;
        int m = min(32, cnt - j0);
        int t = 0;
        for (; t + 4 <= m; t += 4) {
            int s0 = __shfl_sync(0xffffffffu, sreg, t);
            int s1 = __shfl_sync(0xffffffffu, sreg, t + 1);
            int s2 = __shfl_sync(0xffffffffu, sreg, t + 2);
            int s3 = __shfl_sync(0xffffffffu, sreg, t + 3);
            uint4 m0 = g_msg[s0 * 32 + lane];
            uint4 m1 = g_msg[s1 * 32 + lane];
            uint4 m2 = g_msg[s2 * 32 + lane];
            uint4 m3 = g_msg[s3 * 32 + lane];
            acc_msg(m0, ax, ah);
            acc_msg(m1, ax, ah);
            acc_msg(m2, ax, ah);
            acc_msg(m3, ax, ah);
        }
        for (; t < m; t++) {
            int src = __shfl_sync(0xffffffffu, sreg, t);
            uint4 mm = g_msg[src * 32 + lane];
            acc_msg(mm, ax, ah);
        }
    }
    float nn = -rsqrtf(fmaxf((float)cnt, 1.0f));
    half2 pa = __floats2half2_rn(ax.x * nn, ax.y * nn);
    half2 pb = __floats2half2_rn(ax.z * nn, ax.w * nn);
    half2 qa = __floats2half2_rn(ah.x * nn, ah.y * nn);
    half2 qb = __floats2half2_rn(ah.z * nn, ah.w * nn);
    size_t baseA = (size_t)n * KDIM + lane * 4;
    *(uint2*)&g_Ah[baseA + 128] = make_uint2(*(uint32_t*)&pa, *(uint32_t*)&pb);
    *(uint2*)&g_Ah[baseA + 384] = make_uint2(*(uint32_t*)&qa, *(uint32_t*)&qb);
}

// ---------------- W^T concat, single fp16 ----------------
__global__ void k_wcat(const float* __restrict__ W_rx, const float* __restrict__ W_rh,
                       const float* __restrict__ W_ux, const float* __restrict__ W_uh,
                       const float* __restrict__ W_cx, const float* __restrict__ W_ch) {
    int idx = blockIdx.x * blockDim.x + threadIdx.x;
    if (idx >= KDIM * JDIM) return;
    int n = idx >> 9, k = idx & 511;
    int kb = k >> 7, jb = n >> 7;
    int f = k & 127, h = n & 127;
    const float* src = nullptr;
    if (jb == 0)      src = (kb < 2) ? W_rx : W_rh;
    else if (jb == 1) src = (kb < 2) ? W_ux : W_uh;
    else if (jb == 2) src = (kb < 2) ? W_cx : nullptr;
    else              src = (kb >= 2) ? W_ch : nullptr;
    float v = src ? src[(kb & 1) * (FDIM * FDIM) + f * FDIM + h] : 0.f;
    g_Wh[idx] = __float2half_rn(v);
}

// ---------------- HMMA GEMM (fp16 A, fp16 W single), double-buffered, occ 2 ----------------
#define STG   32768
#define SA    0
#define SB    16384
#define SMEM_GEMM 65536

__global__ __launch_bounds__(256, 2) void k_gemm_mma() {
    extern __shared__ char smem[];
    uint32_t sb = smem_u32(smem);
    int tid = threadIdx.x, wid = tid >> 5, lane = tid & 31;
    int row0 = blockIdx.x * 128;
    int n0g = blockIdx.y * 128;
    int wm = (wid & 1) * 64;
    int wn = (wid >> 1) * 32;

    // zero-block skip: y==2 (Cx) uses K-blocks [0,256); y==3 (Ch) uses [256,512)
    int s_beg = (blockIdx.y == 3) ? 4 : 0;
    int s_end = (blockIdx.y == 2) ? 4 : 8;

    float d[4][4][4];
#pragma unroll
    for (int i = 0; i < 4; i++)
#pragma unroll
        for (int j = 0; j < 4; j++)
#pragma unroll
            for (int q = 0; q < 4; q++) d[i][j][q] = 0.f;

    int a_row = wm + (lane & 15);
    int a_kb  = (lane >> 4) * 16;
    int b_row = wn + (lane & 7) + ((lane >> 4) << 3);
    int b_kb  = ((lane >> 3) & 1) * 16;

    const char* pA = (const char*)g_Ah;
    const char* pB = (const char*)g_Wh;

    auto load_stage = [&](int s, int buf) {
        uint32_t base = sb + buf * STG;
#pragma unroll
        for (int it = 0; it < 4; it++) {
            int id = tid + it * 256;
            int r = id >> 3, c = id & 7;
            uint32_t off = SWZ128((uint32_t)(r * 128 + c * 16));
            int row = row0 + r;
            long ga = ((long)row * KDIM + s * 64) * 2 + c * 16;
            int vsz = (row < N_NODES) ? 16 : 0;
            cp16(base + SA + off, pA + ga, vsz);
            long gb = ((long)(n0g + r) * KDIM + s * 64) * 2 + c * 16;
            cp16(base + SB + off, pB + gb, 16);
        }
    };

    load_stage(s_beg, 0);
    CP_COMMIT();

#pragma unroll 1
    for (int s = s_beg; s < s_end; s++) {
        int buf = (s - s_beg) & 1;
        if (s + 1 < s_end) {
            load_stage(s + 1, buf ^ 1);
            CP_COMMIT();
            CP_WAIT1();
        } else {
            CP_WAIT0();
        }
        __syncthreads();

        uint32_t base = sb + buf * STG;
#pragma unroll
        for (int kk = 0; kk < 4; kk++) {
            uint32_t af[4][4];
#pragma unroll
            for (int mf = 0; mf < 4; mf++) {
                uint32_t boff = SWZ128((uint32_t)((a_row + mf * 16) * 128 + kk * 32 + a_kb));
                ldsm_x4(base + SA + boff, af[mf][0], af[mf][1], af[mf][2], af[mf][3]);
            }
            uint32_t bf[4][2];
#pragma unroll
            for (int pf = 0; pf < 2; pf++) {
                uint32_t boff = SWZ128((uint32_t)((b_row + pf * 16) * 128 + kk * 32 + b_kb));
                ldsm_x4(base + SB + boff, bf[2*pf][0], bf[2*pf][1], bf[2*pf+1][0], bf[2*pf+1][1]);
            }
#pragma unroll
            for (int mf = 0; mf < 4; mf++)
#pragma unroll
                for (int nf = 0; nf < 4; nf++) {
                    float* dd = d[mf][nf];
                    mma_f16(dd[0], dd[1], dd[2], dd[3],
                            af[mf][0], af[mf][1], af[mf][2], af[mf][3],
                            bf[nf][0], bf[nf][1]);
                }
        }
        __syncthreads();
    }

#pragma unroll
    for (int mf = 0; mf < 4; mf++) {
        int r0 = row0 + wm + mf * 16 + (lane >> 2);
        int c0 = n0g + wn + (lane & 3) * 2;
#pragma unroll
        for (int nf = 0; nf < 4; nf++) {
            float* dd = d[mf][nf];
            int c = c0 + nf * 8;
            if (r0 < N_NODES)
                *(float2*)&g_G[(size_t)r0 * JDIM + c] = make_float2(dd[0], dd[1]);
            if (r0 + 8 < N_NODES)
                *(float2*)&g_G[(size_t)(r0 + 8) * JDIM + c] = make_float2(dd[2], dd[3]);
        }
    }
}

__device__ __forceinline__ float sigm(float z) { return 1.0f / (1.0f + expf(-z)); }

__global__ void k_epilogue(const float* __restrict__ hx,
                           const float* __restrict__ b_rx, const float* __restrict__ b_rh,
                           const float* __restrict__ b_ux, const float* __restrict__ b_uh,
                           const float* __restrict__ b_cx, const float* __restrict__ b_ch,
                           float* __restrict__ out) {
    int idx = blockIdx.x * blockDim.x + threadIdx.x;
    if (idx >= N_NODES * FDIM) return;
    int n = idx >> 7, h = idx & 127;
    const float* g = &g_G[(size_t)n * JDIM];
    float R  = g[h];
    float U  = g[128 + h];
    float Cx = g[256 + h];
    float Ch = g[384 + h];
    float r = sigm(R + b_rx[h] + b_rh[h]);
    float u = sigm(U + b_ux[h] + b_uh[h]);
    float c = sigm(Cx + b_cx[h] + (Ch + b_ch[h]) * r);
    out[idx] = u * hx[idx] + (1.0f - u) * c;
}

// ---------------- launch ----------------
extern "C" void kernel_launch(void* const* d_in, const int* in_sizes, int n_in,
                              void* d_out, int out_size) {
    const int*   ei   = (const int*)d_in[0];
    const float* x    = (const float*)d_in[1];
    const float* hx   = (const float*)d_in[2];
    const float* W_rx = (const float*)d_in[3];
    const float* b_rx = (const float*)d_in[4];
    const float* W_rh = (const float*)d_in[5];
    const float* b_rh = (const float*)d_in[6];
    const float* W_ux = (const float*)d_in[7];
    const float* b_ux = (const float*)d_in[8];
    const float* W_uh = (const float*)d_in[9];
    const float* b_uh = (const float*)d_in[10];
    const float* W_cx = (const float*)d_in[11];
    const float* b_cx = (const float*)d_in[12];
    const float* W_ch = (const float*)d_in[13];
    const float* b_ch = (const float*)d_in[14];
    float* out = (float*)d_out;

    cudaFuncSetAttribute(k_gemm_mma, cudaFuncAttributeMaxDynamicSharedMemorySize, SMEM_GEMM);

    // CSR build
    k_zero_cnt<<<(N_NODES + 255) / 256, 256>>>();
    k_deg_i<<<(N_EDGES + 255) / 256, 256>>>(ei);
    k_scan<<<196, 256>>>();
    k_fill<<<(N_EDGES + 255) / 256, 256>>>(ei);
    // node prep
    k_scale<<<(N_NODES * 32 + 255) / 256, 256>>>((const float4*)x, (const float4*)hx);
    // aggregation (gather)
    k_gather<<<(N_NODES + 7) / 8, 256>>>();
    // weights
    k_wcat<<<(KDIM * JDIM + 255) / 256, 256>>>(W_rx, W_rh, W_ux, W_uh, W_cx, W_ch);
    // GEMM
    {
        dim3 grid((N_NODES + 127) / 128, 4);
        k_gemm_mma<<<grid, 256, SMEM_GEMM>>>();
    }
    // fused gates + GRU update
    k_epilogue<<<(N_NODES * FDIM + 255) / 256, 256>>>(hx, b_rx, b_rh, b_ux, b_uh,
                                                      b_cx, b_ch, out);
}

// round 10
// speedup vs baseline: 5.1056x; 1.0554x over previous
#include <cuda_runtime.h>
#include <cuda_fp16.h>
#include <math.h>
#include <stdint.h>

#define N_NODES 50000
#define N_EDGES 1600000
#define FDIM 128
#define KDIM 512
#define JDIM 512

// ---------------- device scratch (no allocations allowed) ----------------
__device__ int    g_cnt[N_NODES];        // in-degree (int)
__device__ int    g_ptr[N_NODES];        // CSR row starts
__device__ int    g_cur[N_NODES];        // fill cursors
__device__ int    g_total;               // atomic ticket for block offsets
__device__ int    g_csr[N_EDGES];        // src ids grouped by dst
__device__ uint4  g_msg[N_NODES * 32];   // packed fp16: {x*norm (4h), hx*norm (4h)} per lane
__device__ __half g_Ah[(size_t)N_NODES * KDIM];   // A=[x|px|hx|ph], fp16
__device__ __half g_Wh[KDIM * JDIM];     // W^T [n=512][k=512] fp16
__device__ __half g_Gh[(size_t)N_NODES * JDIM];  // GEMM output [N x 512] fp16

// ---------------- helpers ----------------
__device__ __forceinline__ uint32_t smem_u32(const void* p) {
    uint32_t a;
    asm("{ .reg .u64 t; cvta.to.shared.u64 t, %1; cvt.u32.u64 %0, t; }" : "=r"(a) : "l"(p));
    return a;
}
#define SWZ128(off) ((off) ^ (((off) >> 3) & 0x70))

__device__ __forceinline__ void ldsm_x4(uint32_t addr, uint32_t& r0, uint32_t& r1,
                                        uint32_t& r2, uint32_t& r3) {
    asm volatile("ldmatrix.sync.aligned.m8n8.x4.shared.b16 {%0,%1,%2,%3}, [%4];"
                 : "=r"(r0), "=r"(r1), "=r"(r2), "=r"(r3) : "r"(addr));
}

__device__ __forceinline__ void mma_f16(float& d0, float& d1, float& d2, float& d3,
                                        uint32_t a0, uint32_t a1, uint32_t a2, uint32_t a3,
                                        uint32_t b0, uint32_t b1) {
    asm volatile(
        "mma.sync.aligned.m16n8k16.row.col.f32.f16.f16.f32 "
        "{%0,%1,%2,%3}, {%4,%5,%6,%7}, {%8,%9}, {%0,%1,%2,%3};"
        : "+f"(d0), "+f"(d1), "+f"(d2), "+f"(d3)
        : "r"(a0), "r"(a1), "r"(a2), "r"(a3), "r"(b0), "r"(b1));
}

__device__ __forceinline__ void cp16(uint32_t dst, const void* src, int srcsize) {
    asm volatile("cp.async.cg.shared.global [%0], [%1], 16, %2;"
                 :: "r"(dst), "l"(src), "r"(srcsize) : "memory");
}
#define CP_COMMIT() asm volatile("cp.async.commit_group;" ::: "memory")
#define CP_WAIT1()  asm volatile("cp.async.wait_group 1;" ::: "memory")
#define CP_WAIT0()  asm volatile("cp.async.wait_group 0;" ::: "memory")

// ---------------- CSR build ----------------
__global__ void k_zero_cnt() {
    int i = blockIdx.x * blockDim.x + threadIdx.x;
    if (i < N_NODES) g_cnt[i] = 0;
    if (i == 0) g_total = 0;
}

// 4 edges per thread, MLP=4 on the atomics
__global__ void k_deg_i(const int* __restrict__ ei) {
    int e4 = blockIdx.x * blockDim.x + threadIdx.x;
    if (e4 >= N_EDGES / 4) return;
    int4 d4 = ((const int4*)(ei + N_EDGES))[e4];
    atomicAdd(&g_cnt[d4.x], 1);
    atomicAdd(&g_cnt[d4.y], 1);
    atomicAdd(&g_cnt[d4.z], 1);
    atomicAdd(&g_cnt[d4.w], 1);
}

// single-kernel scan: per-block inclusive scan + atomic ticket for block base.
__global__ void k_scan() {
    __shared__ int sh[256];
    __shared__ int base;
    int tid = threadIdx.x;
    int i = blockIdx.x * 256 + tid;
    int v = (i < N_NODES) ? g_cnt[i] : 0;
    sh[tid] = v;
    __syncthreads();
    for (int o = 1; o < 256; o <<= 1) {
        int t = (tid >= o) ? sh[tid - o] : 0;
        __syncthreads();
        sh[tid] += t;
        __syncthreads();
    }
    if (tid == 255) base = atomicAdd(&g_total, sh[255]);
    __syncthreads();
    if (i < N_NODES) {
        int excl = sh[tid] - v + base;
        g_ptr[i] = excl;
        g_cur[i] = excl;
    }
}

// 4 edges per thread, int4 loads, 4 independent atomic chains
__global__ void k_fill(const int* __restrict__ ei) {
    int e4 = blockIdx.x * blockDim.x + threadIdx.x;
    if (e4 >= N_EDGES / 4) return;
    int4 s4 = ((const int4*)ei)[e4];
    int4 d4 = ((const int4*)(ei + N_EDGES))[e4];
    int p0 = atomicAdd(&g_cur[d4.x], 1);
    int p1 = atomicAdd(&g_cur[d4.y], 1);
    int p2 = atomicAdd(&g_cur[d4.z], 1);
    int p3 = atomicAdd(&g_cur[d4.w], 1);
    g_csr[p0] = s4.x;
    g_csr[p1] = s4.y;
    g_csr[p2] = s4.z;
    g_csr[p3] = s4.w;
}

// ---------------- scale: packed fp16 msg + A blocks 0 (x), 2 (hx) fp16 ----------------
__global__ void k_scale(const float4* __restrict__ x4, const float4* __restrict__ h4) {
    int i = blockIdx.x * blockDim.x + threadIdx.x;  // over N*32 float4
    if (i >= N_NODES * 32) return;
    int n = i >> 5, c4 = i & 31;
    float nrm = rsqrtf(fmaxf((float)g_cnt[n], 1.0f));
    float4 xv = x4[i];
    float4 hv = h4[i];
    half2 xa = __floats2half2_rn(xv.x, xv.y);
    half2 xb = __floats2half2_rn(xv.z, xv.w);
    half2 ha = __floats2half2_rn(hv.x, hv.y);
    half2 hb = __floats2half2_rn(hv.z, hv.w);
    size_t baseA = (size_t)n * KDIM + c4 * 4;
    *(uint2*)&g_Ah[baseA]       = make_uint2(*(uint32_t*)&xa, *(uint32_t*)&xb);
    *(uint2*)&g_Ah[baseA + 256] = make_uint2(*(uint32_t*)&ha, *(uint32_t*)&hb);
    half2 x01 = __floats2half2_rn(xv.x * nrm, xv.y * nrm);
    half2 x23 = __floats2half2_rn(xv.z * nrm, xv.w * nrm);
    half2 hx01 = __floats2half2_rn(hv.x * nrm, hv.y * nrm);
    half2 hx23 = __floats2half2_rn(hv.z * nrm, hv.w * nrm);
    uint4 m;
    m.x = *(uint32_t*)&x01;  m.y = *(uint32_t*)&x23;
    m.z = *(uint32_t*)&hx01; m.w = *(uint32_t*)&hx23;
    g_msg[n * 32 + c4] = m;
}

// ---------------- gather: warp per dst node, writes A blocks 1 (px), 3 (ph) ----------------
__device__ __forceinline__ void acc_msg(uint4 mm, float4& ax, float4& ah) {
    float2 f0 = __half22float2(*(half2*)&mm.x);
    float2 f1 = __half22float2(*(half2*)&mm.y);
    float2 f2 = __half22float2(*(half2*)&mm.z);
    float2 f3 = __half22float2(*(half2*)&mm.w);
    ax.x += f0.x; ax.y += f0.y; ax.z += f1.x; ax.w += f1.y;
    ah.x += f2.x; ah.y += f2.y; ah.z += f3.x; ah.w += f3.y;
}

__global__ __launch_bounds__(256) void k_gather() {
    int wid = threadIdx.x >> 5, lane = threadIdx.x & 31;
    int n = blockIdx.x * 8 + wid;
    if (n >= N_NODES) return;
    int start = g_ptr[n];
    int cnt = g_cnt[n];
    float4 ax = make_float4(0.f, 0.f, 0.f, 0.f);
    float4 ah = make_float4(0.f, 0.f, 0.f, 0.f);
    for (int j0 = 0; j0 < cnt; j0 += 32) {
        int my = j0 + lane;
        int sreg = (my < cnt) ? g_csr[start + my] : 0;
        int m = min(32, cnt - j0);
        int t = 0;
        for (; t + 4 <= m; t += 4) {
            int s0 = __shfl_sync(0xffffffffu, sreg, t);
            int s1 = __shfl_sync(0xffffffffu, sreg, t + 1);
            int s2 = __shfl_sync(0xffffffffu, sreg, t + 2);
            int s3 = __shfl_sync(0xffffffffu, sreg, t + 3);
            uint4 m0 = g_msg[s0 * 32 + lane];
            uint4 m1 = g_msg[s1 * 32 + lane];
            uint4 m2 = g_msg[s2 * 32 + lane];
            uint4 m3 = g_msg[s3 * 32 + lane];
            acc_msg(m0, ax, ah);
            acc_msg(m1, ax, ah);
            acc_msg(m2, ax, ah);
            acc_msg(m3, ax, ah);
        }
        for (; t < m; t++) {
            int src = __shfl_sync(0xffffffffu, sreg, t);
            uint4 mm = g_msg[src * 32 + lane];
            acc_msg(mm, ax, ah);
        }
    }
    float nn = -rsqrtf(fmaxf((float)cnt, 1.0f));
    half2 pa = __floats2half2_rn(ax.x * nn, ax.y * nn);
    half2 pb = __floats2half2_rn(ax.z * nn, ax.w * nn);
    half2 qa = __floats2half2_rn(ah.x * nn, ah.y * nn);
    half2 qb = __floats2half2_rn(ah.z * nn, ah.w * nn);
    size_t baseA = (size_t)n * KDIM + lane * 4;
    *(uint2*)&g_Ah[baseA + 128] = make_uint2(*(uint32_t*)&pa, *(uint32_t*)&pb);
    *(uint2*)&g_Ah[baseA + 384] = make_uint2(*(uint32_t*)&qa, *(uint32_t*)&qb);
}

// ---------------- W^T concat, single fp16 ----------------
__global__ void k_wcat(const float* __restrict__ W_rx, const float* __restrict__ W_rh,
                       const float* __restrict__ W_ux, const float* __restrict__ W_uh,
                       const float* __restrict__ W_cx, const float* __restrict__ W_ch) {
    int idx = blockIdx.x * blockDim.x + threadIdx.x;
    if (idx >= KDIM * JDIM) return;
    int n = idx >> 9, k = idx & 511;
    int kb = k >> 7, jb = n >> 7;
    int f = k & 127, h = n & 127;
    const float* src = nullptr;
    if (jb == 0)      src = (kb < 2) ? W_rx : W_rh;
    else if (jb == 1) src = (kb < 2) ? W_ux : W_uh;
    else if (jb == 2) src = (kb < 2) ? W_cx : nullptr;
    else              src = (kb >= 2) ? W_ch : nullptr;
    float v = src ? src[(kb & 1) * (FDIM * FDIM) + f * FDIM + h] : 0.f;
    g_Wh[idx] = __float2half_rn(v);
}

// ---------------- HMMA GEMM (fp16 A, fp16 W), double-buffered, occ 2, fp16 out ----------------
#define STG   32768
#define SA    0
#define SB    16384
#define SMEM_GEMM 65536

__global__ __launch_bounds__(256, 2) void k_gemm_mma() {
    extern __shared__ char smem[];
    uint32_t sb = smem_u32(smem);
    int tid = threadIdx.x, wid = tid >> 5, lane = tid & 31;
    int row0 = blockIdx.x * 128;
    int n0g = blockIdx.y * 128;
    int wm = (wid & 1) * 64;
    int wn = (wid >> 1) * 32;

    // zero-block skip: y==2 (Cx) uses K-blocks [0,256); y==3 (Ch) uses [256,512)
    int s_beg = (blockIdx.y == 3) ? 4 : 0;
    int s_end = (blockIdx.y == 2) ? 4 : 8;

    float d[4][4][4];
#pragma unroll
    for (int i = 0; i < 4; i++)
#pragma unroll
        for (int j = 0; j < 4; j++)
#pragma unroll
            for (int q = 0; q < 4; q++) d[i][j][q] = 0.f;

    int a_row = wm + (lane & 15);
    int a_kb  = (lane >> 4) * 16;
    int b_row = wn + (lane & 7) + ((lane >> 4) << 3);
    int b_kb  = ((lane >> 3) & 1) * 16;

    const char* pA = (const char*)g_Ah;
    const char* pB = (const char*)g_Wh;

    auto load_stage = [&](int s, int buf) {
        uint32_t base = sb + buf * STG;
#pragma unroll
        for (int it = 0; it < 4; it++) {
            int id = tid + it * 256;
            int r = id >> 3, c = id & 7;
            uint32_t off = SWZ128((uint32_t)(r * 128 + c * 16));
            int row = row0 + r;
            long ga = ((long)row * KDIM + s * 64) * 2 + c * 16;
            int vsz = (row < N_NODES) ? 16 : 0;
            cp16(base + SA + off, pA + ga, vsz);
            long gb = ((long)(n0g + r) * KDIM + s * 64) * 2 + c * 16;
            cp16(base + SB + off, pB + gb, 16);
        }
    };

    load_stage(s_beg, 0);
    CP_COMMIT();

#pragma unroll 1
    for (int s = s_beg; s < s_end; s++) {
        int buf = (s - s_beg) & 1;
        if (s + 1 < s_end) {
            load_stage(s + 1, buf ^ 1);
            CP_COMMIT();
            CP_WAIT1();
        } else {
            CP_WAIT0();
        }
        __syncthreads();

        uint32_t base = sb + buf * STG;
#pragma unroll
        for (int kk = 0; kk < 4; kk++) {
            uint32_t af[4][4];
#pragma unroll
            for (int mf = 0; mf < 4; mf++) {
                uint32_t boff = SWZ128((uint32_t)((a_row + mf * 16) * 128 + kk * 32 + a_kb));
                ldsm_x4(base + SA + boff, af[mf][0], af[mf][1], af[mf][2], af[mf][3]);
            }
            uint32_t bf[4][2];
#pragma unroll
            for (int pf = 0; pf < 2; pf++) {
                uint32_t boff = SWZ128((uint32_t)((b_row + pf * 16) * 128 + kk * 32 + b_kb));
                ldsm_x4(base + SB + boff, bf[2*pf][0], bf[2*pf][1], bf[2*pf+1][0], bf[2*pf+1][1]);
            }
#pragma unroll
            for (int mf = 0; mf < 4; mf++)
#pragma unroll
                for (int nf = 0; nf < 4; nf++) {
                    float* dd = d[mf][nf];
                    mma_f16(dd[0], dd[1], dd[2], dd[3],
                            af[mf][0], af[mf][1], af[mf][2], af[mf][3],
                            bf[nf][0], bf[nf][1]);
                }
        }
        __syncthreads();
    }

    // store as fp16
#pragma unroll
    for (int mf = 0; mf < 4; mf++) {
        int r0 = row0 + wm + mf * 16 + (lane >> 2);
        int c0 = n0g + wn + (lane & 3) * 2;
#pragma unroll
        for (int nf = 0; nf < 4; nf++) {
            float* dd = d[mf][nf];
            int c = c0 + nf * 8;
            half2 v01 = __floats2half2_rn(dd[0], dd[1]);
            half2 v23 = __floats2half2_rn(dd[2], dd[3]);
            if (r0 < N_NODES)
                *(half2*)&g_Gh[(size_t)r0 * JDIM + c] = v01;
            if (r0 + 8 < N_NODES)
                *(half2*)&g_Gh[(size_t)(r0 + 8) * JDIM + c] = v23;
        }
    }
}

__device__ __forceinline__ float sigm(float z) { return 1.0f / (1.0f + expf(-z)); }

// 2 cols per thread via half2
__global__ void k_epilogue(const float* __restrict__ hx,
                           const float* __restrict__ b_rx, const float* __restrict__ b_rh,
                           const float* __restrict__ b_ux, const float* __restrict__ b_uh,
                           const float* __restrict__ b_cx, const float* __restrict__ b_ch,
                           float* __restrict__ out) {
    int idx = blockIdx.x * blockDim.x + threadIdx.x;  // over N*64
    if (idx >= N_NODES * 64) return;
    int n = idx >> 6, hp = idx & 63;
    int h = hp * 2;
    const __half* g = &g_Gh[(size_t)n * JDIM];
    float2 R  = __half22float2(*(const half2*)&g[h]);
    float2 U  = __half22float2(*(const half2*)&g[128 + h]);
    float2 Cx = __half22float2(*(const half2*)&g[256 + h]);
    float2 Ch = __half22float2(*(const half2*)&g[384 + h]);
    float2 hv = *(const float2*)&hx[n * FDIM + h];
    float2 o;
    {
        float r = sigm(R.x + b_rx[h] + b_rh[h]);
        float u = sigm(U.x + b_ux[h] + b_uh[h]);
        float c = sigm(Cx.x + b_cx[h] + (Ch.x + b_ch[h]) * r);
        o.x = u * hv.x + (1.0f - u) * c;
    }
    {
        float r = sigm(R.y + b_rx[h+1] + b_rh[h+1]);
        float u = sigm(U.y + b_ux[h+1] + b_uh[h+1]);
        float c = sigm(Cx.y + b_cx[h+1] + (Ch.y + b_ch[h+1]) * r);
        o.y = u * hv.y + (1.0f - u) * c;
    }
    *(float2*)&out[n * FDIM + h] = o;
}

// ---------------- launch ----------------
extern "C" void kernel_launch(void* const* d_in, const int* in_sizes, int n_in,
                              void* d_out, int out_size) {
    const int*   ei   = (const int*)d_in[0];
    const float* x    = (const float*)d_in[1];
    const float* hx   = (const float*)d_in[2];
    const float* W_rx = (const float*)d_in[3];
    const float* b_rx = (const float*)d_in[4];
    const float* W_rh = (const float*)d_in[5];
    const float* b_rh = (const float*)d_in[6];
    const float* W_ux = (const float*)d_in[7];
    const float* b_ux = (const float*)d_in[8];
    const float* W_uh = (const float*)d_in[9];
    const float* b_uh = (const float*)d_in[10];
    const float* W_cx = (const float*)d_in[11];
    const float* b_cx = (const float*)d_in[12];
    const float* W_ch = (const float*)d_in[13];
    const float* b_ch = (const float*)d_in[14];
    float* out = (float*)d_out;

    cudaFuncSetAttribute(k_gemm_mma, cudaFuncAttributeMaxDynamicSharedMemorySize, SMEM_GEMM);

    // CSR build
    k_zero_cnt<<<(N_NODES + 255) / 256, 256>>>();
    k_deg_i<<<(N_EDGES / 4 + 255) / 256, 256>>>(ei);
    k_scan<<<196, 256>>>();
    k_fill<<<(N_EDGES / 4 + 255) / 256, 256>>>(ei);
    // node prep
    k_scale<<<(N_NODES * 32 + 255) / 256, 256>>>((const float4*)x, (const float4*)hx);
    // aggregation (gather)
    k_gather<<<(N_NODES + 7) / 8, 256>>>();
    // weights
    k_wcat<<<(KDIM * JDIM + 255) / 256, 256>>>(W_rx, W_rh, W_ux, W_uh, W_cx, W_ch);
    // GEMM
    {
        dim3 grid((N_NODES + 127) / 128, 4);
        k_gemm_mma<<<grid, 256, SMEM_GEMM>>>();
    }
    // fused gates + GRU update
    k_epilogue<<<(N_NODES * 64 + 255) / 256, 256>>>(hx, b_rx, b_rh, b_ux, b_uh,
                                                    b_cx, b_ch, out);
}